// round 1
// baseline (speedup 1.0000x reference)
#include <cuda_runtime.h>
#include <math.h>

#define GG    4096
#define HH    512
#define FF    128
#define NPS   64
#define TWOH  1024
#define FOURH 2048

// ---------------- scratch (device globals; no allocation allowed) ----------
__device__ float g_z[GG * FOURH];   // z = q_star @ R + bias   (33.5 MB)
__device__ float g_c[GG * HH];      // LSTM cell state
__device__ float g_w[GG * FF];      // w_g = h_g @ MW^T
__device__ float g_s[GG * FF];      // s_g = sum_n a_n f_n
__device__ float g_h1[HH];          // iter-1 h (same for all segments)
__device__ float g_c1[HH];          // iter-1 c
__device__ float g_w1[FF];          // iter-1 w (same for all segments)
__device__ float g_bias2[FOURH];    // rb + h1 @ R_top  (effective iter-2 bias)

__device__ __forceinline__ float hsig(float x) {
    return __saturatef(fmaf(0.2f, x, 0.5f));
}

// ---------------- f32x2 packed-FMA helpers (FFMA2) -------------------------
__device__ __forceinline__ unsigned long long pack2(float x) {
    unsigned long long r; unsigned u = __float_as_uint(x);
    asm("mov.b64 %0, {%1, %1};" : "=l"(r) : "r"(u));
    return r;
}
__device__ __forceinline__ void fma2(unsigned long long& d,
                                     unsigned long long a,
                                     unsigned long long b) {
    asm("fma.rn.f32x2 %0, %1, %2, %0;" : "+l"(d) : "l"(a), "l"(b));
}
__device__ __forceinline__ float2 unp2(unsigned long long v) {
    float2 r; asm("mov.b64 {%0, %1}, %2;" : "=f"(r.x), "=f"(r.y) : "l"(v));
    return r;
}

// ---------------- K0: iteration-1 analytic prologue ------------------------
// q_star = 0  ->  z1 = recurrent_bias (one vector, same for every segment)
__global__ void k0_init(const float* __restrict__ rb) {
    int h = threadIdx.x;                      // 512 threads
    float zi = rb[h], zc = rb[2 * HH + h], zo = rb[3 * HH + h];
    float c  = hsig(zi) * tanhf(zc);          // f * c0 = 0
    g_c1[h] = c;
    g_h1[h] = hsig(zo) * tanhf(c);
}

__global__ __launch_bounds__(256) void k0_bcast() {
    int i = blockIdx.x * 256 + threadIdx.x;   // < GG*HH
    g_c[i] = g_c1[i & (HH - 1)];
}

// w1[f] = sum_k MW[f,k] * h1[k]
__global__ void k0_w1(const float* __restrict__ MW) {
    int f = threadIdx.x;                      // 128 threads
    float acc = 0.f;
    for (int k = 0; k < HH; k++) acc = fmaf(MW[(size_t)f * HH + k], g_h1[k], acc);
    g_w1[f] = acc;
}

// bias2[n] = rb[n] + sum_k h1[k] * R[k, n]   (folds h1 @ R_top into bias)
__global__ __launch_bounds__(256) void k0_bias2(const float* __restrict__ R,
                                                const float* __restrict__ rb) {
    __shared__ float h1s[HH];
    int n = blockIdx.x * 256 + threadIdx.x;   // < 2048
    for (int k = threadIdx.x; k < HH; k += 256) h1s[k] = g_h1[k];
    __syncthreads();
    float acc = rb[n];
    for (int k = 0; k < HH; k++) acc = fmaf(h1s[k], R[(size_t)k * FOURH + n], acc);
    g_bias2[n] = acc;
}

// ---------------- K1: LSTM gate update -------------------------------------
__global__ __launch_bounds__(256) void k1_gates(float* __restrict__ out) {
    int i  = blockIdx.x * 256 + threadIdx.x;  // < GG*HH
    int hh = i & (HH - 1);
    int g  = i >> 9;
    const float* zr = g_z + (size_t)g * FOURH;
    float zi = zr[hh], zf = zr[HH + hh], zc = zr[2 * HH + hh], zo = zr[3 * HH + hh];
    float c = hsig(zf) * g_c[i] + hsig(zi) * tanhf(zc);
    g_c[i] = c;
    out[(size_t)g * TWOH + hh] = hsig(zo) * tanhf(c);   // h into q_star[:, :H]
}

// ---------------- K2: w = h @ MW^T   [4096,512]x[128,512]^T -> [4096,128] --
__global__ __launch_bounds__(256) void k2_gemm(const float* __restrict__ hmat,
                                               const float* __restrict__ MW) {
    __shared__ float As[32][36];    // [k][m]
    __shared__ float Bs[32][132];   // [k][f]
    int tid = threadIdx.x;
    int m0  = blockIdx.x * 32;
    float acc[4][4];
#pragma unroll
    for (int i = 0; i < 4; i++)
#pragma unroll
        for (int j = 0; j < 4; j++) acc[i][j] = 0.f;
    int tm = (tid >> 5) << 2;       // 8 m-groups * 4
    int tn = (tid & 31) << 2;       // 32 f-groups * 4
    for (int kt = 0; kt < HH; kt += 32) {
        {
            int row = tid >> 3, c4 = (tid & 7) << 2;
            float4 v = *(const float4*)(hmat + (size_t)(m0 + row) * TWOH + kt + c4);
            As[c4 + 0][row] = v.x; As[c4 + 1][row] = v.y;
            As[c4 + 2][row] = v.z; As[c4 + 3][row] = v.w;
        }
#pragma unroll
        for (int i = 0; i < 4; i++) {
            int idx = tid + i * 256;
            int f = idx >> 3, c4 = (idx & 7) << 2;
            float4 v = *(const float4*)(MW + (size_t)f * HH + kt + c4);
            Bs[c4 + 0][f] = v.x; Bs[c4 + 1][f] = v.y;
            Bs[c4 + 2][f] = v.z; Bs[c4 + 3][f] = v.w;
        }
        __syncthreads();
#pragma unroll
        for (int k = 0; k < 32; k++) {
            float4 a = *(const float4*)&As[k][tm];
            float4 b = *(const float4*)&Bs[k][tn];
            float av[4] = {a.x, a.y, a.z, a.w};
            float bv[4] = {b.x, b.y, b.z, b.w};
#pragma unroll
            for (int i = 0; i < 4; i++)
#pragma unroll
                for (int j = 0; j < 4; j++) acc[i][j] = fmaf(av[i], bv[j], acc[i][j]);
        }
        __syncthreads();
    }
#pragma unroll
    for (int i = 0; i < 4; i++)
#pragma unroll
        for (int j = 0; j < 4; j++)
            g_w[(size_t)(m0 + tm + i) * FF + tn + j] = acc[i][j];
}

// ---------------- K3: per-segment softmax + weighted feature sum -----------
__global__ __launch_bounds__(128) void k3_seg(const float* __restrict__ feat,
                                              const float* __restrict__ wts,
                                              int use_w1) {
    int g = blockIdx.x;
    int tid = threadIdx.x;                  // 128 threads
    __shared__ float fs[NPS][FF + 4];       // 64 x 132 (padded)
    __shared__ float ws[FF];
    __shared__ float as[NPS];
    __shared__ float red[8];

    const float4* fp = (const float4*)(feat + (size_t)g * NPS * FF);
#pragma unroll
    for (int it = 0; it < 16; it++) {
        int idx = tid + (it << 7);          // 0..2047 float4s
        float4 v = fp[idx];
        int node = idx >> 5;
        int col  = (idx & 31) << 2;
        *(float4*)&fs[node][col] = v;
    }
    const float* wp = use_w1 ? g_w1 : (g_w + (size_t)g * FF);
    ws[tid] = wp[tid];
    __syncthreads();

    float e = -1e30f;
    if (tid < NPS) {
        float acc = 0.f;
#pragma unroll
        for (int f = 0; f < FF; f += 4) {
            float4 fv = *(const float4*)&fs[tid][f];
            float4 wv = *(const float4*)&ws[f];
            acc = fmaf(fv.x, wv.x, acc); acc = fmaf(fv.y, wv.y, acc);
            acc = fmaf(fv.z, wv.z, acc); acc = fmaf(fv.w, wv.w, acc);
        }
        e = acc;
    }
    float mx = e;
#pragma unroll
    for (int o = 16; o > 0; o >>= 1) mx = fmaxf(mx, __shfl_xor_sync(0xffffffffu, mx, o));
    if ((tid & 31) == 0) red[tid >> 5] = mx;
    __syncthreads();
    mx = fmaxf(fmaxf(red[0], red[1]), fmaxf(red[2], red[3]));

    float ex = 0.f;
    if (tid < NPS) ex = __expf(e - mx) * wts[(size_t)g * NPS + tid];
    float sm = ex;
#pragma unroll
    for (int o = 16; o > 0; o >>= 1) sm += __shfl_xor_sync(0xffffffffu, sm, o);
    if ((tid & 31) == 0) red[4 + (tid >> 5)] = sm;
    __syncthreads();
    sm = (red[4] + red[5]) + (red[6] + red[7]);
    if (tid < NPS) as[tid] = ex / sm;
    __syncthreads();

    float acc = 0.f;                         // s[f] = sum_n a[n]*f[n,f]
#pragma unroll 16
    for (int n = 0; n < NPS; n++) acc = fmaf(as[n], fs[n][tid], acc);
    g_s[(size_t)g * FF + tid] = acc;
}

// ---------------- K4: r = s @ MW + mb   [4096,128]x[128,512] ---------------
__global__ __launch_bounds__(256) void k4_gemm(const float* __restrict__ MW,
                                               const float* __restrict__ mb,
                                               float* __restrict__ out) {
    __shared__ float As[16][68];
    __shared__ __align__(16) float Bs[16][64];
    int tid = threadIdx.x;
    int m0 = blockIdx.x * 64;
    int n0 = blockIdx.y * 64;
    float acc[4][4];
#pragma unroll
    for (int i = 0; i < 4; i++)
#pragma unroll
        for (int j = 0; j < 4; j++) acc[i][j] = 0.f;
    int tm = (tid >> 4) << 2;
    int tn = (tid & 15) << 2;
    for (int kt = 0; kt < FF; kt += 16) {
        {
            int row = tid >> 2, c4 = (tid & 3) << 2;
            float4 v = *(const float4*)(g_s + (size_t)(m0 + row) * FF + kt + c4);
            As[c4 + 0][row] = v.x; As[c4 + 1][row] = v.y;
            As[c4 + 2][row] = v.z; As[c4 + 3][row] = v.w;
        }
        {
            int kr = tid >> 4, nc = (tid & 15) << 2;
            float4 v = *(const float4*)(MW + (size_t)(kt + kr) * HH + n0 + nc);
            *(float4*)&Bs[kr][nc] = v;
        }
        __syncthreads();
#pragma unroll
        for (int k = 0; k < 16; k++) {
            float4 a = *(const float4*)&As[k][tm];
            float4 b = *(const float4*)&Bs[k][tn];
            float av[4] = {a.x, a.y, a.z, a.w};
            float bv[4] = {b.x, b.y, b.z, b.w};
#pragma unroll
            for (int i = 0; i < 4; i++)
#pragma unroll
                for (int j = 0; j < 4; j++) acc[i][j] = fmaf(av[i], bv[j], acc[i][j]);
        }
        __syncthreads();
    }
#pragma unroll
    for (int i = 0; i < 4; i++)
#pragma unroll
        for (int j = 0; j < 4; j++)
            out[(size_t)(m0 + tm + i) * TWOH + HH + n0 + tn + j] =
                acc[i][j] + mb[n0 + tn + j];
}

// ---------------- K5: big recurrent GEMM, f32x2 packed FMAs ----------------
// C[M=4096, N=2048] = A[M, K] @ B[K, 2048] + bias ; A row-major with lda.
// BM=BN=128, BK=8, 256 threads, 8x8 per thread (accs as f32x2 n-pairs).
__global__ __launch_bounds__(256) void k5_gemm(const float* __restrict__ A,
                                               int lda, int K,
                                               const float* __restrict__ B,
                                               const float* __restrict__ bias,
                                               int use_b2) {
    __shared__ unsigned long long Asd[2][8][128];   // A duplicated (x,x) pairs
    __shared__ __align__(16) float Bs[2][8][128];
    int tid  = threadIdx.x;
    int nblk = blockIdx.x << 7;
    int mblk = blockIdx.y << 7;
    int arow = tid >> 1, ak = (tid & 1) << 2;
    int brow = tid >> 5, bc = (tid & 31) << 2;
    const float* Aptr = A + (size_t)(mblk + arow) * lda + ak;
    const float* Bptr = B + (size_t)brow * FOURH + nblk + bc;

    float4 av = *(const float4*)Aptr;
    float4 bv = *(const float4*)Bptr;
    Asd[0][ak + 0][arow] = pack2(av.x);
    Asd[0][ak + 1][arow] = pack2(av.y);
    Asd[0][ak + 2][arow] = pack2(av.z);
    Asd[0][ak + 3][arow] = pack2(av.w);
    *(float4*)&Bs[0][brow][bc] = bv;
    __syncthreads();

    unsigned long long acc[8][4];
#pragma unroll
    for (int i = 0; i < 8; i++)
#pragma unroll
        for (int j = 0; j < 4; j++) acc[i][j] = 0ull;

    int m0 = (tid >> 4) << 3;
    int n0 = (tid & 15) << 3;
    int ntiles = K >> 3;
    for (int t = 0; t < ntiles; t++) {
        int buf = t & 1;
        if (t + 1 < ntiles) {
            av = *(const float4*)(Aptr + ((t + 1) << 3));
            bv = *(const float4*)(Bptr + (size_t)((t + 1) << 3) * FOURH);
        }
#pragma unroll
        for (int k = 0; k < 8; k++) {
            unsigned long long a[8];
#pragma unroll
            for (int i = 0; i < 8; i++) a[i] = Asd[buf][k][m0 + i];
            ulonglong2 b01 = *(const ulonglong2*)&Bs[buf][k][n0];
            ulonglong2 b23 = *(const ulonglong2*)&Bs[buf][k][n0 + 4];
#pragma unroll
            for (int i = 0; i < 8; i++) {
                fma2(acc[i][0], a[i], b01.x);
                fma2(acc[i][1], a[i], b01.y);
                fma2(acc[i][2], a[i], b23.x);
                fma2(acc[i][3], a[i], b23.y);
            }
        }
        if (t + 1 < ntiles) {
            int nb = buf ^ 1;
            Asd[nb][ak + 0][arow] = pack2(av.x);
            Asd[nb][ak + 1][arow] = pack2(av.y);
            Asd[nb][ak + 2][arow] = pack2(av.z);
            Asd[nb][ak + 3][arow] = pack2(av.w);
            *(float4*)&Bs[nb][brow][bc] = bv;
        }
        __syncthreads();
    }

    const float* bp = use_b2 ? g_bias2 : bias;
    int col = nblk + n0;
    float bvv[8];
#pragma unroll
    for (int j = 0; j < 8; j++) bvv[j] = bp[col + j];
#pragma unroll
    for (int i = 0; i < 8; i++) {
        float2 p0 = unp2(acc[i][0]), p1 = unp2(acc[i][1]);
        float2 p2 = unp2(acc[i][2]), p3 = unp2(acc[i][3]);
        float* cr = g_z + (size_t)(mblk + m0 + i) * FOURH + col;
        float4 o0 = make_float4(p0.x + bvv[0], p0.y + bvv[1], p1.x + bvv[2], p1.y + bvv[3]);
        float4 o1 = make_float4(p2.x + bvv[4], p2.y + bvv[5], p3.x + bvv[6], p3.y + bvv[7]);
        *(float4*)cr = o0;
        *(float4*)(cr + 4) = o1;
    }
}

// ---------------- launch ----------------------------------------------------
extern "C" void kernel_launch(void* const* d_in, const int* in_sizes, int n_in,
                              void* d_out, int out_size) {
    const float* feat = (const float*)d_in[0];   // features (1, N, F)
    const float* wts  = (const float*)d_in[1];   // weights  (1, N)
    // d_in[2] = index: with this problem it is exactly n/64 (64 per segment)
    const float* MW   = (const float*)d_in[3];   // m_weight (F, H)
    const float* mb   = (const float*)d_in[4];   // m_bias   (H,)
    const float* R    = (const float*)d_in[5];   // recurrent_kernel (2H, 4H)
    const float* rb   = (const float*)d_in[6];   // recurrent_bias   (4H,)
    float* out = (float*)d_out;                  // q_star (1, G, 2H)

    // ---- iteration 1 (analytic: q_star = 0 -> z = bias, h identical per g)
    k0_init <<<1, HH>>>(rb);
    k0_bcast<<<(GG * HH) / 256, 256>>>();
    k0_w1   <<<1, FF>>>(MW);
    k0_bias2<<<FOURH / 256, 256>>>(R, rb);
    k3_seg  <<<GG, 128>>>(feat, wts, 1);
    k4_gemm <<<dim3(GG / 64, HH / 64), 256>>>(MW, mb, out);   // r1 -> out[:,H:]

    // ---- iteration 2 (h1 folded into bias2 -> half-K GEMM over r only)
    k5_gemm <<<dim3(FOURH / 128, GG / 128), 256>>>(out + HH, TWOH, HH,
                                                   R + (size_t)HH * FOURH, rb, 1);
    k1_gates<<<(GG * HH) / 256, 256>>>(out);
    k2_gemm <<<GG / 32, 256>>>(out, MW);
    k3_seg  <<<GG, 128>>>(feat, wts, 0);
    k4_gemm <<<dim3(GG / 64, HH / 64), 256>>>(MW, mb, out);

    // ---- iteration 3 (full GEMM)
    k5_gemm <<<dim3(FOURH / 128, GG / 128), 256>>>(out, TWOH, TWOH, R, rb, 0);
    k1_gates<<<(GG * HH) / 256, 256>>>(out);
    k2_gemm <<<GG / 32, 256>>>(out, MW);
    k3_seg  <<<GG, 128>>>(feat, wts, 0);
    k4_gemm <<<dim3(GG / 64, HH / 64), 256>>>(MW, mb, out);
}

// round 6
// speedup vs baseline: 1.7855x; 1.7855x over previous
#include <cuda_runtime.h>
#include <cuda_bf16.h>
#include <math.h>
#include <stdint.h>

#define GG    4096
#define HH    512
#define FF    128
#define NPS   64
#define TWOH  1024
#define FOURH 2048

// ---------------- scratch (device globals; no allocation allowed) ----------
// NOTE: device-global symbols must only be referenced from DEVICE code.
// Passing their address from host code silently yields the host shadow
// (readable via ATS on GB300 -> zeros), which caused rounds 3-5 failures.
__device__ float g_z[GG * FOURH];     // z = q_star @ R + bias
__device__ float g_c[GG * HH];        // LSTM cell state
__device__ float g_w[GG * FF];        // w_g = h_g @ MW^T
__device__ float g_s[GG * FF];        // s_g = sum_n a_n f_n
__device__ float g_h1[HH];
__device__ float g_c1[HH];
__device__ float g_w1[FF];
__device__ float g_bias2[FOURH];      // rb + h1 @ R_top
__device__ float g_b2p[8 * FOURH];    // split-K partials for bias2
__device__ __nv_bfloat16 g_ahi[GG * TWOH];      // q_star hi (bf16)
__device__ __nv_bfloat16 g_alo[GG * TWOH];      // q_star lo (bf16)
__device__ __nv_bfloat16 g_bhi[FOURH * TWOH];   // R^T hi   [n][k]
__device__ __nv_bfloat16 g_blo[FOURH * TWOH];   // R^T lo   [n][k]

__device__ __forceinline__ float hsig(float x) {
    return __saturatef(fmaf(0.2f, x, 0.5f));
}
__device__ __forceinline__ void mma16816(float* c, const uint32_t* a,
                                         const uint32_t* b) {
    asm volatile(
        "mma.sync.aligned.m16n8k16.row.col.f32.bf16.bf16.f32 "
        "{%0,%1,%2,%3}, {%4,%5,%6,%7}, {%8,%9}, {%0,%1,%2,%3};"
        : "+f"(c[0]), "+f"(c[1]), "+f"(c[2]), "+f"(c[3])
        : "r"(a[0]), "r"(a[1]), "r"(a[2]), "r"(a[3]), "r"(b[0]), "r"(b[1]));
}

// ---------------- K0: iteration-1 analytic prologue ------------------------
__global__ void k0_init(const float* __restrict__ rb) {
    int h = threadIdx.x;                      // 512 threads
    float zi = rb[h], zc = rb[2 * HH + h], zo = rb[3 * HH + h];
    float c  = hsig(zi) * tanhf(zc);
    g_c1[h] = c;
    g_h1[h] = hsig(zo) * tanhf(c);
}
__global__ __launch_bounds__(256) void k0_bcast() {
    int i = blockIdx.x * 256 + threadIdx.x;
    g_c[i] = g_c1[i & (HH - 1)];
}
__global__ void k0_w1(const float* __restrict__ MW) {
    int f = threadIdx.x;                      // 128 threads
    float acc = 0.f;
    for (int k = 0; k < HH; k++) acc = fmaf(MW[(size_t)f * HH + k], g_h1[k], acc);
    g_w1[f] = acc;
}
__global__ __launch_bounds__(256) void k0_bias2a(const float* __restrict__ R) {
    int id = blockIdx.x * 256 + threadIdx.x;  // 16384
    int n  = id & (FOURH - 1);
    int ch = id >> 11;                        // 0..7
    const float* hp = g_h1 + ch * 64;
    const float* rp = R + (size_t)(ch * 64) * FOURH + n;
    float acc = 0.f;
#pragma unroll 8
    for (int k = 0; k < 64; k++) acc = fmaf(hp[k], rp[(size_t)k * FOURH], acc);
    g_b2p[ch * FOURH + n] = acc;
}
__global__ __launch_bounds__(256) void k0_bias2b(const float* __restrict__ rb) {
    int n = blockIdx.x * 256 + threadIdx.x;   // 2048
    float a = rb[n];
#pragma unroll
    for (int c = 0; c < 8; c++) a += g_b2p[c * FOURH + n];
    g_bias2[n] = a;
}

// ---------------- Kconv: R [1024][2048] fp32 -> R^T hi/lo bf16 [2048][1024] -
__global__ __launch_bounds__(256) void kconv_R(const float* __restrict__ R) {
    __shared__ float tile[32][33];
    int k0 = blockIdx.x * 32, n0 = blockIdx.y * 32;
    int tx = threadIdx.x & 31, ty = threadIdx.x >> 5;  // 32 x 8
#pragma unroll
    for (int i = ty; i < 32; i += 8)
        tile[i][tx] = R[(size_t)(k0 + i) * FOURH + n0 + tx];
    __syncthreads();
#pragma unroll
    for (int i = ty; i < 32; i += 8) {
        float v = tile[tx][i];                 // = R[k0+tx][n0+i]
        __nv_bfloat16 hi = __float2bfloat16(v);
        size_t o = (size_t)(n0 + i) * TWOH + k0 + tx;
        g_bhi[o] = hi;
        g_blo[o] = __float2bfloat16(v - __bfloat162float(hi));
    }
}

// ---------------- K1: LSTM gates (+ emits bf16 hi/lo of h) -----------------
__global__ __launch_bounds__(256) void k1_gates(float* __restrict__ out) {
    int i  = blockIdx.x * 256 + threadIdx.x;
    int hh = i & (HH - 1);
    int g  = i >> 9;
    const float* zr = g_z + (size_t)g * FOURH;
    float zi = zr[hh], zf = zr[HH + hh], zc = zr[2 * HH + hh], zo = zr[3 * HH + hh];
    float c = hsig(zf) * g_c[i] + hsig(zi) * tanhf(zc);
    g_c[i] = c;
    float h = hsig(zo) * tanhf(c);
    size_t o = (size_t)g * TWOH + hh;
    out[o] = h;
    __nv_bfloat16 hi = __float2bfloat16(h);
    g_ahi[o] = hi;
    g_alo[o] = __float2bfloat16(h - __bfloat162float(hi));
}

// ---------------- K2: w = h @ MW^T ------------------------------------------
__global__ __launch_bounds__(256) void k2_gemm(const float* __restrict__ hmat,
                                               const float* __restrict__ MW) {
    __shared__ float As[32][36];
    __shared__ float Bs[32][132];
    int tid = threadIdx.x;
    int m0  = blockIdx.x * 32;
    float acc[4][4];
#pragma unroll
    for (int i = 0; i < 4; i++)
#pragma unroll
        for (int j = 0; j < 4; j++) acc[i][j] = 0.f;
    int tm = (tid >> 5) << 2;
    int tn = (tid & 31) << 2;
    for (int kt = 0; kt < HH; kt += 32) {
        {
            int row = tid >> 3, c4 = (tid & 7) << 2;
            float4 v = *(const float4*)(hmat + (size_t)(m0 + row) * TWOH + kt + c4);
            As[c4 + 0][row] = v.x; As[c4 + 1][row] = v.y;
            As[c4 + 2][row] = v.z; As[c4 + 3][row] = v.w;
        }
#pragma unroll
        for (int i = 0; i < 4; i++) {
            int idx = tid + i * 256;
            int f = idx >> 3, c4 = (idx & 7) << 2;
            float4 v = *(const float4*)(MW + (size_t)f * HH + kt + c4);
            Bs[c4 + 0][f] = v.x; Bs[c4 + 1][f] = v.y;
            Bs[c4 + 2][f] = v.z; Bs[c4 + 3][f] = v.w;
        }
        __syncthreads();
#pragma unroll
        for (int k = 0; k < 32; k++) {
            float4 a = *(const float4*)&As[k][tm];
            float4 b = *(const float4*)&Bs[k][tn];
            float av[4] = {a.x, a.y, a.z, a.w};
            float bv[4] = {b.x, b.y, b.z, b.w};
#pragma unroll
            for (int i = 0; i < 4; i++)
#pragma unroll
                for (int j = 0; j < 4; j++) acc[i][j] = fmaf(av[i], bv[j], acc[i][j]);
        }
        __syncthreads();
    }
#pragma unroll
    for (int i = 0; i < 4; i++)
#pragma unroll
        for (int j = 0; j < 4; j++)
            g_w[(size_t)(m0 + tm + i) * FF + tn + j] = acc[i][j];
}

// ---------------- K3: per-segment softmax + weighted feature sum -----------
__global__ __launch_bounds__(128) void k3_seg(const float* __restrict__ feat,
                                              const float* __restrict__ wts,
                                              int use_w1) {
    int g = blockIdx.x;
    int tid = threadIdx.x;
    __shared__ float fs[NPS][FF + 4];
    __shared__ float ws[FF];
    __shared__ float as[NPS];
    __shared__ float red[8];

    const float4* fp = (const float4*)(feat + (size_t)g * NPS * FF);
#pragma unroll
    for (int it = 0; it < 16; it++) {
        int idx = tid + (it << 7);
        float4 v = fp[idx];
        int node = idx >> 5;
        int col  = (idx & 31) << 2;
        *(float4*)&fs[node][col] = v;
    }
    const float* wp = use_w1 ? g_w1 : (g_w + (size_t)g * FF);
    ws[tid] = wp[tid];
    __syncthreads();

    float e = -1e30f;
    if (tid < NPS) {
        float acc = 0.f;
#pragma unroll
        for (int f = 0; f < FF; f += 4) {
            float4 fv = *(const float4*)&fs[tid][f];
            float4 wv = *(const float4*)&ws[f];
            acc = fmaf(fv.x, wv.x, acc); acc = fmaf(fv.y, wv.y, acc);
            acc = fmaf(fv.z, wv.z, acc); acc = fmaf(fv.w, wv.w, acc);
        }
        e = acc;
    }
    float mx = e;
#pragma unroll
    for (int o = 16; o > 0; o >>= 1) mx = fmaxf(mx, __shfl_xor_sync(0xffffffffu, mx, o));
    if ((tid & 31) == 0) red[tid >> 5] = mx;
    __syncthreads();
    mx = fmaxf(fmaxf(red[0], red[1]), fmaxf(red[2], red[3]));

    float ex = 0.f;
    if (tid < NPS) ex = __expf(e - mx) * wts[(size_t)g * NPS + tid];
    float sm = ex;
#pragma unroll
    for (int o = 16; o > 0; o >>= 1) sm += __shfl_xor_sync(0xffffffffu, sm, o);
    if ((tid & 31) == 0) red[4 + (tid >> 5)] = sm;
    __syncthreads();
    sm = (red[4] + red[5]) + (red[6] + red[7]);
    if (tid < NPS) as[tid] = ex / sm;
    __syncthreads();

    float acc = 0.f;
#pragma unroll 16
    for (int n = 0; n < NPS; n++) acc = fmaf(as[n], fs[n][tid], acc);
    g_s[(size_t)g * FF + tid] = acc;
}

// ---------------- K4: r = s @ MW + mb (+ emits bf16 hi/lo of r) ------------
__global__ __launch_bounds__(256) void k4_gemm(const float* __restrict__ MW,
                                               const float* __restrict__ mb,
                                               float* __restrict__ out) {
    __shared__ float As[16][68];
    __shared__ __align__(16) float Bs[16][64];
    int tid = threadIdx.x;
    int m0 = blockIdx.x * 64;
    int n0 = blockIdx.y * 64;
    float acc[4][4];
#pragma unroll
    for (int i = 0; i < 4; i++)
#pragma unroll
        for (int j = 0; j < 4; j++) acc[i][j] = 0.f;
    int tm = (tid >> 4) << 2;
    int tn = (tid & 15) << 2;
    for (int kt = 0; kt < FF; kt += 16) {
        {
            int row = tid >> 2, c4 = (tid & 3) << 2;
            float4 v = *(const float4*)(g_s + (size_t)(m0 + row) * FF + kt + c4);
            As[c4 + 0][row] = v.x; As[c4 + 1][row] = v.y;
            As[c4 + 2][row] = v.z; As[c4 + 3][row] = v.w;
        }
        {
            int kr = tid >> 4, nc = (tid & 15) << 2;
            float4 v = *(const float4*)(MW + (size_t)(kt + kr) * HH + n0 + nc);
            *(float4*)&Bs[kr][nc] = v;
        }
        __syncthreads();
#pragma unroll
        for (int k = 0; k < 16; k++) {
            float4 a = *(const float4*)&As[k][tm];
            float4 b = *(const float4*)&Bs[k][tn];
            float av[4] = {a.x, a.y, a.z, a.w};
            float bv[4] = {b.x, b.y, b.z, b.w};
#pragma unroll
            for (int i = 0; i < 4; i++)
#pragma unroll
                for (int j = 0; j < 4; j++) acc[i][j] = fmaf(av[i], bv[j], acc[i][j]);
        }
        __syncthreads();
    }
#pragma unroll
    for (int i = 0; i < 4; i++)
#pragma unroll
        for (int j = 0; j < 4; j++) {
            float v = acc[i][j] + mb[n0 + tn + j];
            size_t o = (size_t)(m0 + tm + i) * TWOH + HH + n0 + tn + j;
            out[o] = v;
            __nv_bfloat16 hi = __float2bfloat16(v);
            g_ahi[o] = hi;
            g_alo[o] = __float2bfloat16(v - __bfloat162float(hi));
        }
}

// ---------------- K5: mma.sync bf16 hi/lo split GEMM -----------------------
// g_z[M=4096, N=2048] = A[M,K] @ B^T[N,K] + bias via 3 bf16 products.
// A/B are the device globals g_a*/g_b* addressed via INTEGER offsets
// (device-symbol pointers must not be formed in host code).
// BM=BN=128, BK=16, 8 warps (warp tile 64x32), cp.async double buffering.
#define LDSR 24                        // 16 + 8 pad (bf16); row = 48B (16B-mult)
#define MATE (128 * LDSR)              // 3072 elements per matrix tile
#define STGE (4 * MATE)                // 12288 elements per stage (24576 B)

__global__ __launch_bounds__(256, 2) void k5_mma(
    int aoff, int boff, int K, const float* __restrict__ rb, int use_b2)
{
    const __nv_bfloat16* __restrict__ Ahi = g_ahi + aoff;
    const __nv_bfloat16* __restrict__ Alo = g_alo + aoff;
    const __nv_bfloat16* __restrict__ Bhi = g_bhi + boff;
    const __nv_bfloat16* __restrict__ Blo = g_blo + boff;

    __shared__ __align__(16) __nv_bfloat16 smem[2 * STGE];   // 49152 bytes
    int tid = threadIdx.x;
    int lane = tid & 31, wid = tid >> 5;
    int wm = wid >> 2, wn = wid & 3;          // 2 x 4 warp grid
    int nblk = blockIdx.x << 7, mblk = blockIdx.y << 7;
    int g8 = lane >> 2;                       // fragment row group 0..7
    int t2 = (lane & 3) << 1;                 // fragment k pair base 0,2,4,6

    // per-thread staging slot: row tid>>1, 16B chunk (tid&1) of each matrix
    int sr = tid >> 1;
    int sc = (tid & 1) << 3;
    uint32_t sbase;
    asm("{ .reg .u64 t; cvta.to.shared.u64 t, %1; cvt.u32.u64 %0, t; }"
        : "=r"(sbase) : "l"((const void*)smem));
    uint32_t soff = (uint32_t)(sr * LDSR + sc) * 2;

    float acc[4][4][4];
#pragma unroll
    for (int a = 0; a < 4; a++)
#pragma unroll
        for (int b = 0; b < 4; b++)
#pragma unroll
            for (int c = 0; c < 4; c++) acc[a][b][c] = 0.f;

    int nch = K >> 4;

#define LOAD_STAGE(T, ST) do {                                                  \
    int kg_ = (T) << 4;                                                         \
    uint32_t sb_ = sbase + (uint32_t)(ST) * (STGE * 2) + soff;                  \
    const __nv_bfloat16* a_ = Ahi + (size_t)(mblk + sr) * TWOH + kg_ + sc;      \
    const __nv_bfloat16* b_ = Bhi + (size_t)(nblk + sr) * TWOH + kg_ + sc;      \
    asm volatile("cp.async.cg.shared.global [%0], [%1], 16;"                    \
                 :: "r"(sb_), "l"(a_) : "memory");                              \
    asm volatile("cp.async.cg.shared.global [%0], [%1], 16;"                    \
                 :: "r"(sb_ + MATE * 2), "l"(Alo + (a_ - Ahi)) : "memory");     \
    asm volatile("cp.async.cg.shared.global [%0], [%1], 16;"                    \
                 :: "r"(sb_ + 2 * MATE * 2), "l"(b_) : "memory");               \
    asm volatile("cp.async.cg.shared.global [%0], [%1], 16;"                    \
                 :: "r"(sb_ + 3 * MATE * 2), "l"(Blo + (b_ - Bhi)) : "memory"); \
    asm volatile("cp.async.commit_group;" ::: "memory");                       \
} while (0)

    LOAD_STAGE(0, 0);
    asm volatile("cp.async.wait_group 0;" ::: "memory");
    __syncthreads();

    for (int t = 0; t < nch; t++) {
        if (t + 1 < nch) LOAD_STAGE(t + 1, (t + 1) & 1);

        const __nv_bfloat16* stage = smem + (size_t)(t & 1) * STGE;
        int kc = t2;                           // k pair base within the 16-chunk
        // ---- B fragments: 4 n-tiles, hi and lo
        uint32_t bh[4][2], bl[4][2];
#pragma unroll
        for (int nt = 0; nt < 4; nt++) {
            int nr = wn * 32 + nt * 8 + g8;
            const __nv_bfloat16* Bh = stage + 2 * MATE + nr * LDSR;
            const __nv_bfloat16* Bl = Bh + MATE;
            bh[nt][0] = *(const uint32_t*)(Bh + kc);
            bh[nt][1] = *(const uint32_t*)(Bh + kc + 8);
            bl[nt][0] = *(const uint32_t*)(Bl + kc);
            bl[nt][1] = *(const uint32_t*)(Bl + kc + 8);
        }
#pragma unroll
        for (int mt = 0; mt < 4; mt++) {
            int mr = wm * 64 + mt * 16 + g8;
            const __nv_bfloat16* Ah = stage + mr * LDSR;
            const __nv_bfloat16* Al = Ah + MATE;
            uint32_t ahf[4], alf[4];
            ahf[0] = *(const uint32_t*)(Ah + kc);
            ahf[1] = *(const uint32_t*)(Ah + 8 * LDSR + kc);
            ahf[2] = *(const uint32_t*)(Ah + kc + 8);
            ahf[3] = *(const uint32_t*)(Ah + 8 * LDSR + kc + 8);
            alf[0] = *(const uint32_t*)(Al + kc);
            alf[1] = *(const uint32_t*)(Al + 8 * LDSR + kc);
            alf[2] = *(const uint32_t*)(Al + kc + 8);
            alf[3] = *(const uint32_t*)(Al + 8 * LDSR + kc + 8);
#pragma unroll
            for (int nt = 0; nt < 4; nt++) {
                mma16816(acc[mt][nt], ahf, bh[nt]);
                mma16816(acc[mt][nt], ahf, bl[nt]);
                mma16816(acc[mt][nt], alf, bh[nt]);
            }
        }

        if (t + 1 < nch) {
            asm volatile("cp.async.wait_group 0;" ::: "memory");
            __syncthreads();
        }
    }

    // ---- epilogue: bias add + store to g_z
    const float* bp = use_b2 ? g_bias2 : rb;
#pragma unroll
    for (int mt = 0; mt < 4; mt++) {
#pragma unroll
        for (int nt = 0; nt < 4; nt++) {
            int m = mblk + wm * 64 + mt * 16 + g8;
            int n = nblk + wn * 32 + nt * 8 + t2;
            float b0 = bp[n], b1 = bp[n + 1];
            float2 v0 = make_float2(acc[mt][nt][0] + b0, acc[mt][nt][1] + b1);
            float2 v1 = make_float2(acc[mt][nt][2] + b0, acc[mt][nt][3] + b1);
            *(float2*)(g_z + (size_t)m * FOURH + n) = v0;
            *(float2*)(g_z + (size_t)(m + 8) * FOURH + n) = v1;
        }
    }
}

// ---------------- launch ----------------------------------------------------
extern "C" void kernel_launch(void* const* d_in, const int* in_sizes, int n_in,
                              void* d_out, int out_size) {
    const float* feat = (const float*)d_in[0];   // features (1, N, F)
    const float* wts  = (const float*)d_in[1];   // weights  (1, N)
    const float* MW   = (const float*)d_in[3];   // m_weight (F, H)
    const float* mb   = (const float*)d_in[4];   // m_bias   (H,)
    const float* R    = (const float*)d_in[5];   // recurrent_kernel (2H, 4H)
    const float* rb   = (const float*)d_in[6];   // recurrent_bias   (4H,)
    float* out = (float*)d_out;                  // q_star (1, G, 2H)

    // ---- prologue: convert R once; analytic iteration 1
    kconv_R <<<dim3(TWOH / 32, FOURH / 32), 256>>>(R);
    k0_init <<<1, HH>>>(rb);
    k0_bcast<<<(GG * HH) / 256, 256>>>();
    k0_w1   <<<1, FF>>>(MW);
    k0_bias2a<<<64, 256>>>(R);
    k0_bias2b<<<FOURH / 256, 256>>>(rb);
    k3_seg  <<<GG, 128>>>(feat, wts, 1);
    k4_gemm <<<dim3(GG / 64, HH / 64), 256>>>(MW, mb, out);

    // ---- iteration 2 (h1 folded into bias2 -> half-K GEMM over r only)
    k5_mma  <<<dim3(FOURH / 128, GG / 128), 256>>>(HH, HH, HH, rb, 1);
    k1_gates<<<(GG * HH) / 256, 256>>>(out);
    k2_gemm <<<GG / 32, 256>>>(out, MW);
    k3_seg  <<<GG, 128>>>(feat, wts, 0);
    k4_gemm <<<dim3(GG / 64, HH / 64), 256>>>(MW, mb, out);

    // ---- iteration 3 (full K = 2H)
    k5_mma  <<<dim3(FOURH / 128, GG / 128), 256>>>(0, 0, TWOH, rb, 0);
    k1_gates<<<(GG * HH) / 256, 256>>>(out);
    k2_gemm <<<GG / 32, 256>>>(out, MW);
    k3_seg  <<<GG, 128>>>(feat, wts, 0);
    k4_gemm <<<dim3(GG / 64, HH / 64), 256>>>(MW, mb, out);
}

// round 7
// speedup vs baseline: 2.0060x; 1.1235x over previous
#include <cuda_runtime.h>
#include <cuda_bf16.h>
#include <math.h>
#include <stdint.h>

#define GG    4096
#define HH    512
#define FF    128
#define NPS   64
#define TWOH  1024
#define FOURH 2048

// ---------------- scratch (device globals; no allocation allowed) ----------
// NOTE: device-global symbols must only be referenced from DEVICE code.
__device__ float g_z[GG * FOURH];     // z = q_star @ R + bias
__device__ float g_c[GG * HH];        // LSTM cell state
__device__ float g_w[GG * FF];        // w_g = h_g @ MW^T
__device__ float g_s[GG * FF];        // s_g = sum_n a_n f_n
__device__ float g_h1[HH];
__device__ float g_c1[HH];
__device__ float g_w1[FF];
__device__ float g_bias2[FOURH];      // rb + h1 @ R_top
__device__ float g_b2p[8 * FOURH];    // split-K partials for bias2
__device__ __nv_bfloat16 g_ahi[GG * TWOH];      // q_star hi (bf16)
__device__ __nv_bfloat16 g_alo[GG * TWOH];      // q_star lo (bf16)
__device__ __nv_bfloat16 g_bhi[FOURH * TWOH];   // R^T hi   [n][k]
__device__ __nv_bfloat16 g_blo[FOURH * TWOH];   // R^T lo   [n][k]

__device__ __forceinline__ float hsig(float x) {
    return __saturatef(fmaf(0.2f, x, 0.5f));
}
__device__ __forceinline__ void mma16816(float* c, const uint32_t* a,
                                         const uint32_t* b) {
    asm volatile(
        "mma.sync.aligned.m16n8k16.row.col.f32.bf16.bf16.f32 "
        "{%0,%1,%2,%3}, {%4,%5,%6,%7}, {%8,%9}, {%0,%1,%2,%3};"
        : "+f"(c[0]), "+f"(c[1]), "+f"(c[2]), "+f"(c[3])
        : "r"(a[0]), "r"(a[1]), "r"(a[2]), "r"(a[3]), "r"(b[0]), "r"(b[1]));
}

// ---------------- K0: iteration-1 analytic prologue ------------------------
__global__ void k0_init(const float* __restrict__ rb) {
    int h = threadIdx.x;                      // 512 threads
    float zi = rb[h], zc = rb[2 * HH + h], zo = rb[3 * HH + h];
    float c  = hsig(zi) * tanhf(zc);
    g_c1[h] = c;
    g_h1[h] = hsig(zo) * tanhf(c);
}
__global__ __launch_bounds__(256) void k0_bcast() {
    int i = blockIdx.x * 256 + threadIdx.x;
    g_c[i] = g_c1[i & (HH - 1)];
}
// w1[f] = sum_k MW[f,k] * h1[k] — one warp per f (16 blocks x 8 warps)
__global__ __launch_bounds__(256) void k0_w1(const float* __restrict__ MW) {
    int warp = blockIdx.x * 8 + (threadIdx.x >> 5);   // 0..127
    int lane = threadIdx.x & 31;
    const float* row = MW + (size_t)warp * HH;
    float acc = 0.f;
#pragma unroll 4
    for (int k = lane; k < HH; k += 32) acc = fmaf(row[k], g_h1[k], acc);
#pragma unroll
    for (int o = 16; o > 0; o >>= 1) acc += __shfl_xor_sync(0xffffffffu, acc, o);
    if (lane == 0) g_w1[warp] = acc;
}
__global__ __launch_bounds__(256) void k0_bias2a(const float* __restrict__ R) {
    int id = blockIdx.x * 256 + threadIdx.x;  // 16384
    int n  = id & (FOURH - 1);
    int ch = id >> 11;                        // 0..7
    const float* hp = g_h1 + ch * 64;
    const float* rp = R + (size_t)(ch * 64) * FOURH + n;
    float acc = 0.f;
#pragma unroll 8
    for (int k = 0; k < 64; k++) acc = fmaf(hp[k], rp[(size_t)k * FOURH], acc);
    g_b2p[ch * FOURH + n] = acc;
}
__global__ __launch_bounds__(256) void k0_bias2b(const float* __restrict__ rb) {
    int n = blockIdx.x * 256 + threadIdx.x;   // 2048
    float a = rb[n];
#pragma unroll
    for (int c = 0; c < 8; c++) a += g_b2p[c * FOURH + n];
    g_bias2[n] = a;
}

// ---------------- Kconv: R [1024][2048] fp32 -> R^T hi/lo bf16 [2048][1024] -
__global__ __launch_bounds__(256) void kconv_R(const float* __restrict__ R) {
    __shared__ float tile[32][33];
    int k0 = blockIdx.x * 32, n0 = blockIdx.y * 32;
    int tx = threadIdx.x & 31, ty = threadIdx.x >> 5;  // 32 x 8
#pragma unroll
    for (int i = ty; i < 32; i += 8)
        tile[i][tx] = R[(size_t)(k0 + i) * FOURH + n0 + tx];
    __syncthreads();
#pragma unroll
    for (int i = ty; i < 32; i += 8) {
        float v = tile[tx][i];                 // = R[k0+tx][n0+i]
        __nv_bfloat16 hi = __float2bfloat16(v);
        size_t o = (size_t)(n0 + i) * TWOH + k0 + tx;
        g_bhi[o] = hi;
        g_blo[o] = __float2bfloat16(v - __bfloat162float(hi));
    }
}

// ---------------- K1: LSTM gates (+ emits bf16 hi/lo of h) -----------------
__global__ __launch_bounds__(256) void k1_gates(float* __restrict__ out) {
    int i  = blockIdx.x * 256 + threadIdx.x;
    int hh = i & (HH - 1);
    int g  = i >> 9;
    const float* zr = g_z + (size_t)g * FOURH;
    float zi = zr[hh], zf = zr[HH + hh], zc = zr[2 * HH + hh], zo = zr[3 * HH + hh];
    float c = hsig(zf) * g_c[i] + hsig(zi) * tanhf(zc);
    g_c[i] = c;
    float h = hsig(zo) * tanhf(c);
    size_t o = (size_t)g * TWOH + hh;
    out[o] = h;
    __nv_bfloat16 hi = __float2bfloat16(h);
    g_ahi[o] = hi;
    g_alo[o] = __float2bfloat16(h - __bfloat162float(hi));
}

// ---------------- K2: w = h @ MW^T ------------------------------------------
__global__ __launch_bounds__(256) void k2_gemm(const float* __restrict__ hmat,
                                               const float* __restrict__ MW) {
    __shared__ float As[32][36];
    __shared__ float Bs[32][132];
    int tid = threadIdx.x;
    int m0  = blockIdx.x * 32;
    float acc[4][4];
#pragma unroll
    for (int i = 0; i < 4; i++)
#pragma unroll
        for (int j = 0; j < 4; j++) acc[i][j] = 0.f;
    int tm = (tid >> 5) << 2;
    int tn = (tid & 31) << 2;
    for (int kt = 0; kt < HH; kt += 32) {
        {
            int row = tid >> 3, c4 = (tid & 7) << 2;
            float4 v = *(const float4*)(hmat + (size_t)(m0 + row) * TWOH + kt + c4);
            As[c4 + 0][row] = v.x; As[c4 + 1][row] = v.y;
            As[c4 + 2][row] = v.z; As[c4 + 3][row] = v.w;
        }
#pragma unroll
        for (int i = 0; i < 4; i++) {
            int idx = tid + i * 256;
            int f = idx >> 3, c4 = (idx & 7) << 2;
            float4 v = *(const float4*)(MW + (size_t)f * HH + kt + c4);
            Bs[c4 + 0][f] = v.x; Bs[c4 + 1][f] = v.y;
            Bs[c4 + 2][f] = v.z; Bs[c4 + 3][f] = v.w;
        }
        __syncthreads();
#pragma unroll
        for (int k = 0; k < 32; k++) {
            float4 a = *(const float4*)&As[k][tm];
            float4 b = *(const float4*)&Bs[k][tn];
            float av[4] = {a.x, a.y, a.z, a.w};
            float bv[4] = {b.x, b.y, b.z, b.w};
#pragma unroll
            for (int i = 0; i < 4; i++)
#pragma unroll
                for (int j = 0; j < 4; j++) acc[i][j] = fmaf(av[i], bv[j], acc[i][j]);
        }
        __syncthreads();
    }
#pragma unroll
    for (int i = 0; i < 4; i++)
#pragma unroll
        for (int j = 0; j < 4; j++)
            g_w[(size_t)(m0 + tm + i) * FF + tn + j] = acc[i][j];
}

// ---------------- K3: per-segment softmax + weighted feature sum -----------
__global__ __launch_bounds__(128) void k3_seg(const float* __restrict__ feat,
                                              const float* __restrict__ wts,
                                              int use_w1) {
    int g = blockIdx.x;
    int tid = threadIdx.x;
    __shared__ float fs[NPS][FF + 4];
    __shared__ float ws[FF];
    __shared__ float as[NPS];
    __shared__ float red[8];

    const float4* fp = (const float4*)(feat + (size_t)g * NPS * FF);
#pragma unroll
    for (int it = 0; it < 16; it++) {
        int idx = tid + (it << 7);
        float4 v = fp[idx];
        int node = idx >> 5;
        int col  = (idx & 31) << 2;
        *(float4*)&fs[node][col] = v;
    }
    const float* wp = use_w1 ? g_w1 : (g_w + (size_t)g * FF);
    ws[tid] = wp[tid];
    __syncthreads();

    float e = -1e30f;
    if (tid < NPS) {
        float acc = 0.f;
#pragma unroll
        for (int f = 0; f < FF; f += 4) {
            float4 fv = *(const float4*)&fs[tid][f];
            float4 wv = *(const float4*)&ws[f];
            acc = fmaf(fv.x, wv.x, acc); acc = fmaf(fv.y, wv.y, acc);
            acc = fmaf(fv.z, wv.z, acc); acc = fmaf(fv.w, wv.w, acc);
        }
        e = acc;
    }
    float mx = e;
#pragma unroll
    for (int o = 16; o > 0; o >>= 1) mx = fmaxf(mx, __shfl_xor_sync(0xffffffffu, mx, o));
    if ((tid & 31) == 0) red[tid >> 5] = mx;
    __syncthreads();
    mx = fmaxf(fmaxf(red[0], red[1]), fmaxf(red[2], red[3]));

    float ex = 0.f;
    if (tid < NPS) ex = __expf(e - mx) * wts[(size_t)g * NPS + tid];
    float sm = ex;
#pragma unroll
    for (int o = 16; o > 0; o >>= 1) sm += __shfl_xor_sync(0xffffffffu, sm, o);
    if ((tid & 31) == 0) red[4 + (tid >> 5)] = sm;
    __syncthreads();
    sm = (red[4] + red[5]) + (red[6] + red[7]);
    if (tid < NPS) as[tid] = ex / sm;
    __syncthreads();

    float acc = 0.f;
#pragma unroll 16
    for (int n = 0; n < NPS; n++) acc = fmaf(as[n], fs[n][tid], acc);
    g_s[(size_t)g * FF + tid] = acc;
}

// ---------------- K4: r = s @ MW + mb (+ emits bf16 hi/lo of r) ------------
__global__ __launch_bounds__(256) void k4_gemm(const float* __restrict__ MW,
                                               const float* __restrict__ mb,
                                               float* __restrict__ out) {
    __shared__ float As[16][68];
    __shared__ __align__(16) float Bs[16][64];
    int tid = threadIdx.x;
    int m0 = blockIdx.x * 64;
    int n0 = blockIdx.y * 64;
    float acc[4][4];
#pragma unroll
    for (int i = 0; i < 4; i++)
#pragma unroll
        for (int j = 0; j < 4; j++) acc[i][j] = 0.f;
    int tm = (tid >> 4) << 2;
    int tn = (tid & 15) << 2;
    for (int kt = 0; kt < FF; kt += 16) {
        {
            int row = tid >> 2, c4 = (tid & 3) << 2;
            float4 v = *(const float4*)(g_s + (size_t)(m0 + row) * FF + kt + c4);
            As[c4 + 0][row] = v.x; As[c4 + 1][row] = v.y;
            As[c4 + 2][row] = v.z; As[c4 + 3][row] = v.w;
        }
        {
            int kr = tid >> 4, nc = (tid & 15) << 2;
            float4 v = *(const float4*)(MW + (size_t)(kt + kr) * HH + n0 + nc);
            *(float4*)&Bs[kr][nc] = v;
        }
        __syncthreads();
#pragma unroll
        for (int k = 0; k < 16; k++) {
            float4 a = *(const float4*)&As[k][tm];
            float4 b = *(const float4*)&Bs[k][tn];
            float av[4] = {a.x, a.y, a.z, a.w};
            float bv[4] = {b.x, b.y, b.z, b.w};
#pragma unroll
            for (int i = 0; i < 4; i++)
#pragma unroll
                for (int j = 0; j < 4; j++) acc[i][j] = fmaf(av[i], bv[j], acc[i][j]);
        }
        __syncthreads();
    }
#pragma unroll
    for (int i = 0; i < 4; i++)
#pragma unroll
        for (int j = 0; j < 4; j++) {
            float v = acc[i][j] + mb[n0 + tn + j];
            size_t o = (size_t)(m0 + tm + i) * TWOH + HH + n0 + tn + j;
            out[o] = v;
            __nv_bfloat16 hi = __float2bfloat16(v);
            g_ahi[o] = hi;
            g_alo[o] = __float2bfloat16(v - __bfloat162float(hi));
        }
}

// ---------------- K5: mma.sync bf16 hi/lo split GEMM -----------------------
// g_z[M=4096, N=2048] = A[M,K] @ B^T[N,K] + bias via 3 bf16 products.
// BM=BN=128, BK=16, 8 warps (warp tile 64x32), cp.async double buffering,
// ldmatrix.x4 fragment loads (full 128B crossbar wavefronts).
#define LDSR 24                        // 16 + 8 pad (bf16); row = 48B (16B-mult)
#define MATE (128 * LDSR)              // 3072 elements per matrix tile
#define STGE (4 * MATE)                // 12288 elements per stage (24576 B)

__global__ __launch_bounds__(256, 2) void k5_mma(
    int aoff, int boff, int K, const float* __restrict__ rb, int use_b2)
{
    const __nv_bfloat16* __restrict__ Ahi = g_ahi + aoff;
    const __nv_bfloat16* __restrict__ Alo = g_alo + aoff;
    const __nv_bfloat16* __restrict__ Bhi = g_bhi + boff;
    const __nv_bfloat16* __restrict__ Blo = g_blo + boff;

    __shared__ __align__(16) __nv_bfloat16 smem[2 * STGE];   // 49152 bytes
    int tid = threadIdx.x;
    int lane = tid & 31, wid = tid >> 5;
    int wm = wid >> 2, wn = wid & 3;          // 2 x 4 warp grid
    int nblk = blockIdx.x << 7, mblk = blockIdx.y << 7;
    int g8 = lane >> 2;                       // fragment row group 0..7
    int t2 = (lane & 3) << 1;                 // fragment k pair base 0,2,4,6

    // per-thread staging slot: row tid>>1, 16B chunk (tid&1) of each matrix
    int sr = tid >> 1;
    int sc = (tid & 1) << 3;
    uint32_t sbase;
    asm("{ .reg .u64 t; cvta.to.shared.u64 t, %1; cvt.u32.u64 %0, t; }"
        : "=r"(sbase) : "l"((const void*)smem));
    uint32_t soff = (uint32_t)(sr * LDSR + sc) * 2;

    // ldmatrix source addresses (within a stage, byte offsets from stage base):
    // A x4: row = warp_m_base + mt*16 + (lane&15), col = ((lane>>4)<<3)
    uint32_t a_lm = (uint32_t)(((wm * 64) + (lane & 15)) * LDSR +
                               ((lane >> 4) << 3)) * 2;
    // B x4 (2 n-tiles): row = wn*32 + p*16 + ((gq>>1)<<3) + (lane&7),
    //                   col = ((gq&1)<<3), gq = lane>>3
    uint32_t b_lm = (uint32_t)(2 * MATE +
                               ((wn * 32) + (((lane >> 3) >> 1) << 3) + (lane & 7)) * LDSR +
                               (((lane >> 3) & 1) << 3)) * 2;

    float acc[4][4][4];
#pragma unroll
    for (int a = 0; a < 4; a++)
#pragma unroll
        for (int b = 0; b < 4; b++)
#pragma unroll
            for (int c = 0; c < 4; c++) acc[a][b][c] = 0.f;

    int nch = K >> 4;

#define LOAD_STAGE(T, ST) do {                                                  \
    int kg_ = (T) << 4;                                                         \
    uint32_t sb_ = sbase + (uint32_t)(ST) * (STGE * 2) + soff;                  \
    const __nv_bfloat16* a_ = Ahi + (size_t)(mblk + sr) * TWOH + kg_ + sc;      \
    const __nv_bfloat16* b_ = Bhi + (size_t)(nblk + sr) * TWOH + kg_ + sc;      \
    asm volatile("cp.async.cg.shared.global [%0], [%1], 16;"                    \
                 :: "r"(sb_), "l"(a_) : "memory");                              \
    asm volatile("cp.async.cg.shared.global [%0], [%1], 16;"                    \
                 :: "r"(sb_ + MATE * 2), "l"(Alo + (a_ - Ahi)) : "memory");     \
    asm volatile("cp.async.cg.shared.global [%0], [%1], 16;"                    \
                 :: "r"(sb_ + 2 * MATE * 2), "l"(b_) : "memory");               \
    asm volatile("cp.async.cg.shared.global [%0], [%1], 16;"                    \
                 :: "r"(sb_ + 3 * MATE * 2), "l"(Blo + (b_ - Bhi)) : "memory"); \
    asm volatile("cp.async.commit_group;" ::: "memory");                       \
} while (0)

#define LDSM_X4(r0, r1, r2, r3, addr)                                           \
    asm volatile("ldmatrix.sync.aligned.m8n8.x4.shared.b16 {%0,%1,%2,%3}, [%4];"\
        : "=r"(r0), "=r"(r1), "=r"(r2), "=r"(r3) : "r"(addr) : "memory")

    LOAD_STAGE(0, 0);
    asm volatile("cp.async.wait_group 0;" ::: "memory");
    __syncthreads();

    for (int t = 0; t < nch; t++) {
        if (t + 1 < nch) LOAD_STAGE(t + 1, (t + 1) & 1);

        uint32_t sb = sbase + (uint32_t)(t & 1) * (STGE * 2);
        // ---- B fragments: 4 n-tiles (2 ldmatrix.x4 each for hi/lo)
        uint32_t bh[4][2], bl[4][2];
#pragma unroll
        for (int p = 0; p < 2; p++) {
            uint32_t ba = sb + b_lm + (uint32_t)(p * 16 * LDSR) * 2;
            LDSM_X4(bh[2 * p][0], bh[2 * p][1], bh[2 * p + 1][0], bh[2 * p + 1][1], ba);
            LDSM_X4(bl[2 * p][0], bl[2 * p][1], bl[2 * p + 1][0], bl[2 * p + 1][1],
                    ba + (uint32_t)(MATE * 2));
        }
#pragma unroll
        for (int mt = 0; mt < 4; mt++) {
            uint32_t aa = sb + a_lm + (uint32_t)(mt * 16 * LDSR) * 2;
            uint32_t ahf[4], alf[4];
            LDSM_X4(ahf[0], ahf[1], ahf[2], ahf[3], aa);
            LDSM_X4(alf[0], alf[1], alf[2], alf[3], aa + (uint32_t)(MATE * 2));
#pragma unroll
            for (int nt = 0; nt < 4; nt++) {
                mma16816(acc[mt][nt], ahf, bh[nt]);
                mma16816(acc[mt][nt], ahf, bl[nt]);
                mma16816(acc[mt][nt], alf, bh[nt]);
            }
        }

        if (t + 1 < nch) {
            asm volatile("cp.async.wait_group 0;" ::: "memory");
            __syncthreads();
        }
    }

    // ---- epilogue: bias add + store to g_z
    const float* bp = use_b2 ? g_bias2 : rb;
#pragma unroll
    for (int mt = 0; mt < 4; mt++) {
#pragma unroll
        for (int nt = 0; nt < 4; nt++) {
            int m = mblk + wm * 64 + mt * 16 + g8;
            int n = nblk + wn * 32 + nt * 8 + t2;
            float b0 = bp[n], b1 = bp[n + 1];
            float2 v0 = make_float2(acc[mt][nt][0] + b0, acc[mt][nt][1] + b1);
            float2 v1 = make_float2(acc[mt][nt][2] + b0, acc[mt][nt][3] + b1);
            *(float2*)(g_z + (size_t)m * FOURH + n) = v0;
            *(float2*)(g_z + (size_t)(m + 8) * FOURH + n) = v1;
        }
    }
}

// ---------------- launch ----------------------------------------------------
extern "C" void kernel_launch(void* const* d_in, const int* in_sizes, int n_in,
                              void* d_out, int out_size) {
    const float* feat = (const float*)d_in[0];   // features (1, N, F)
    const float* wts  = (const float*)d_in[1];   // weights  (1, N)
    const float* MW   = (const float*)d_in[3];   // m_weight (F, H)
    const float* mb   = (const float*)d_in[4];   // m_bias   (H,)
    const float* R    = (const float*)d_in[5];   // recurrent_kernel (2H, 4H)
    const float* rb   = (const float*)d_in[6];   // recurrent_bias   (4H,)
    float* out = (float*)d_out;                  // q_star (1, G, 2H)

    // ---- prologue: convert R once; analytic iteration 1
    kconv_R <<<dim3(TWOH / 32, FOURH / 32), 256>>>(R);
    k0_init <<<1, HH>>>(rb);
    k0_bcast<<<(GG * HH) / 256, 256>>>();
    k0_w1   <<<16, 256>>>(MW);
    k0_bias2a<<<64, 256>>>(R);
    k0_bias2b<<<FOURH / 256, 256>>>(rb);
    k3_seg  <<<GG, 128>>>(feat, wts, 1);
    k4_gemm <<<dim3(GG / 64, HH / 64), 256>>>(MW, mb, out);

    // ---- iteration 2 (h1 folded into bias2 -> half-K GEMM over r only)
    k5_mma  <<<dim3(FOURH / 128, GG / 128), 256>>>(HH, HH, HH, rb, 1);
    k1_gates<<<(GG * HH) / 256, 256>>>(out);
    k2_gemm <<<GG / 32, 256>>>(out, MW);
    k3_seg  <<<GG, 128>>>(feat, wts, 0);
    k4_gemm <<<dim3(GG / 64, HH / 64), 256>>>(MW, mb, out);

    // ---- iteration 3 (full K = 2H)
    k5_mma  <<<dim3(FOURH / 128, GG / 128), 256>>>(0, 0, TWOH, rb, 0);
    k1_gates<<<(GG * HH) / 256, 256>>>(out);
    k2_gemm <<<GG / 32, 256>>>(out, MW);
    k3_seg  <<<GG, 128>>>(feat, wts, 0);
    k4_gemm <<<dim3(GG / 64, HH / 64), 256>>>(MW, mb, out);
}

// round 8
// speedup vs baseline: 2.1634x; 1.0784x over previous
#include <cuda_runtime.h>
#include <cuda_bf16.h>
#include <math.h>
#include <stdint.h>

#define GG    4096
#define HH    512
#define FF    128
#define NPS   64
#define TWOH  1024
#define FOURH 2048

// ---------------- scratch (device globals; no allocation allowed) ----------
// NOTE: device-global symbols must only be referenced from DEVICE code.
__device__ float g_z[GG * FOURH];     // z = q_star @ R + bias
__device__ float g_c[GG * HH];        // LSTM cell state
__device__ float g_w[GG * FF];        // w_g = h_g @ MW^T
__device__ float g_h1[HH];
__device__ float g_c1[HH];
__device__ float g_w1[FF];
__device__ float g_bias2[FOURH];      // rb + h1 @ R_top
__device__ float g_b2p[8 * FOURH];    // split-K partials for bias2
__device__ __nv_bfloat16 g_ahi[GG * TWOH];      // q_star hi (bf16)
__device__ __nv_bfloat16 g_alo[GG * TWOH];      // q_star lo (bf16)
__device__ __nv_bfloat16 g_bhi[FOURH * TWOH];   // R^T hi   [n][k]
__device__ __nv_bfloat16 g_blo[FOURH * TWOH];   // R^T lo   [n][k]
__device__ __nv_bfloat16 g_shi[GG * FF];        // s hi
__device__ __nv_bfloat16 g_slo[GG * FF];        // s lo
__device__ __nv_bfloat16 g_mwhi[FF * HH];       // MW hi    [f][k]
__device__ __nv_bfloat16 g_mwlo[FF * HH];
__device__ __nv_bfloat16 g_mthi[HH * FF];       // MW^T hi  [h][f]
__device__ __nv_bfloat16 g_mtlo[HH * FF];

__device__ __forceinline__ float hsig(float x) {
    return __saturatef(fmaf(0.2f, x, 0.5f));
}
__device__ __forceinline__ void mma16816(float* c, const uint32_t* a,
                                         const uint32_t* b) {
    asm volatile(
        "mma.sync.aligned.m16n8k16.row.col.f32.bf16.bf16.f32 "
        "{%0,%1,%2,%3}, {%4,%5,%6,%7}, {%8,%9}, {%0,%1,%2,%3};"
        : "+f"(c[0]), "+f"(c[1]), "+f"(c[2]), "+f"(c[3])
        : "r"(a[0]), "r"(a[1]), "r"(a[2]), "r"(a[3]), "r"(b[0]), "r"(b[1]));
}

// ---------------- K0: iteration-1 analytic prologue ------------------------
__global__ void k0_init(const float* __restrict__ rb) {
    int h = threadIdx.x;                      // 512 threads
    float zi = rb[h], zc = rb[2 * HH + h], zo = rb[3 * HH + h];
    float c  = hsig(zi) * tanhf(zc);
    g_c1[h] = c;
    g_h1[h] = hsig(zo) * tanhf(c);
}
__global__ __launch_bounds__(256) void k0_bcast() {
    int i = blockIdx.x * 256 + threadIdx.x;
    g_c[i] = g_c1[i & (HH - 1)];
}
// w1[f] = sum_k MW[f,k] * h1[k] — one warp per f
__global__ __launch_bounds__(256) void k0_w1(const float* __restrict__ MW) {
    int warp = blockIdx.x * 8 + (threadIdx.x >> 5);   // 0..127
    int lane = threadIdx.x & 31;
    const float* row = MW + (size_t)warp * HH;
    float acc = 0.f;
#pragma unroll 4
    for (int k = lane; k < HH; k += 32) acc = fmaf(row[k], g_h1[k], acc);
#pragma unroll
    for (int o = 16; o > 0; o >>= 1) acc += __shfl_xor_sync(0xffffffffu, acc, o);
    if (lane == 0) g_w1[warp] = acc;
}
__global__ __launch_bounds__(256) void k0_bias2a(const float* __restrict__ R) {
    int id = blockIdx.x * 256 + threadIdx.x;  // 16384
    int n  = id & (FOURH - 1);
    int ch = id >> 11;                        // 0..7
    const float* hp = g_h1 + ch * 64;
    const float* rp = R + (size_t)(ch * 64) * FOURH + n;
    float acc = 0.f;
#pragma unroll 8
    for (int k = 0; k < 64; k++) acc = fmaf(hp[k], rp[(size_t)k * FOURH], acc);
    g_b2p[ch * FOURH + n] = acc;
}
__global__ __launch_bounds__(256) void k0_bias2b(const float* __restrict__ rb) {
    int n = blockIdx.x * 256 + threadIdx.x;   // 2048
    float a = rb[n];
#pragma unroll
    for (int c = 0; c < 8; c++) a += g_b2p[c * FOURH + n];
    g_bias2[n] = a;
}

// ---------------- Kconv_R: R fp32 -> R^T hi/lo bf16 [2048][1024] -----------
__global__ __launch_bounds__(256) void kconv_R(const float* __restrict__ R) {
    __shared__ float tile[32][33];
    int k0 = blockIdx.x * 32, n0 = blockIdx.y * 32;
    int tx = threadIdx.x & 31, ty = threadIdx.x >> 5;  // 32 x 8
#pragma unroll
    for (int i = ty; i < 32; i += 8)
        tile[i][tx] = R[(size_t)(k0 + i) * FOURH + n0 + tx];
    __syncthreads();
#pragma unroll
    for (int i = ty; i < 32; i += 8) {
        float v = tile[tx][i];                 // = R[k0+tx][n0+i]
        __nv_bfloat16 hi = __float2bfloat16(v);
        size_t o = (size_t)(n0 + i) * TWOH + k0 + tx;
        g_bhi[o] = hi;
        g_blo[o] = __float2bfloat16(v - __bfloat162float(hi));
    }
}

// ---------------- Kconv_MW: MW fp32 -> bf16 hi/lo (direct + transposed) ----
__global__ __launch_bounds__(256) void kconv_MW(const float* __restrict__ MW) {
    __shared__ float tile[32][33];
    int h0 = blockIdx.x * 32, f0 = blockIdx.y * 32;
    int tx = threadIdx.x & 31, ty = threadIdx.x >> 5;
#pragma unroll
    for (int i = ty; i < 32; i += 8) {
        float v = MW[(size_t)(f0 + i) * HH + h0 + tx];
        tile[i][tx] = v;
        __nv_bfloat16 hi = __float2bfloat16(v);
        size_t o = (size_t)(f0 + i) * HH + h0 + tx;
        g_mwhi[o] = hi;
        g_mwlo[o] = __float2bfloat16(v - __bfloat162float(hi));
    }
    __syncthreads();
#pragma unroll
    for (int i = ty; i < 32; i += 8) {
        float v = tile[tx][i];                 // = MW[f0+tx][h0+i]
        __nv_bfloat16 hi = __float2bfloat16(v);
        size_t o = (size_t)(h0 + i) * FF + f0 + tx;
        g_mthi[o] = hi;
        g_mtlo[o] = __float2bfloat16(v - __bfloat162float(hi));
    }
}

// ---------------- K1: LSTM gates (+ emits bf16 hi/lo of h) -----------------
__global__ __launch_bounds__(256) void k1_gates(float* __restrict__ out) {
    int i  = blockIdx.x * 256 + threadIdx.x;
    int hh = i & (HH - 1);
    int g  = i >> 9;
    const float* zr = g_z + (size_t)g * FOURH;
    float zi = zr[hh], zf = zr[HH + hh], zc = zr[2 * HH + hh], zo = zr[3 * HH + hh];
    float c = hsig(zf) * g_c[i] + hsig(zi) * tanhf(zc);
    g_c[i] = c;
    float h = hsig(zo) * tanhf(c);
    size_t o = (size_t)g * TWOH + hh;
    out[o] = h;
    __nv_bfloat16 hi = __float2bfloat16(h);
    g_ahi[o] = hi;
    g_alo[o] = __float2bfloat16(h - __bfloat162float(hi));
}

// ---------------- K3: per-segment softmax + weighted feature sum -----------
__global__ __launch_bounds__(128) void k3_seg(const float* __restrict__ feat,
                                              const float* __restrict__ wts,
                                              int use_w1) {
    int g = blockIdx.x;
    int tid = threadIdx.x;
    __shared__ float fs[NPS][FF + 4];
    __shared__ float ws[FF];
    __shared__ float as[NPS];
    __shared__ float red[8];

    const float4* fp = (const float4*)(feat + (size_t)g * NPS * FF);
#pragma unroll
    for (int it = 0; it < 16; it++) {
        int idx = tid + (it << 7);
        float4 v = fp[idx];
        int node = idx >> 5;
        int col  = (idx & 31) << 2;
        *(float4*)&fs[node][col] = v;
    }
    const float* wp = use_w1 ? g_w1 : (g_w + (size_t)g * FF);
    ws[tid] = wp[tid];
    __syncthreads();

    float e = -1e30f;
    if (tid < NPS) {
        float acc = 0.f;
#pragma unroll
        for (int f = 0; f < FF; f += 4) {
            float4 fv = *(const float4*)&fs[tid][f];
            float4 wv = *(const float4*)&ws[f];
            acc = fmaf(fv.x, wv.x, acc); acc = fmaf(fv.y, wv.y, acc);
            acc = fmaf(fv.z, wv.z, acc); acc = fmaf(fv.w, wv.w, acc);
        }
        e = acc;
    }
    float mx = e;
#pragma unroll
    for (int o = 16; o > 0; o >>= 1) mx = fmaxf(mx, __shfl_xor_sync(0xffffffffu, mx, o));
    if ((tid & 31) == 0) red[tid >> 5] = mx;
    __syncthreads();
    mx = fmaxf(fmaxf(red[0], red[1]), fmaxf(red[2], red[3]));

    float ex = 0.f;
    if (tid < NPS) ex = __expf(e - mx) * wts[(size_t)g * NPS + tid];
    float sm = ex;
#pragma unroll
    for (int o = 16; o > 0; o >>= 1) sm += __shfl_xor_sync(0xffffffffu, sm, o);
    if ((tid & 31) == 0) red[4 + (tid >> 5)] = sm;
    __syncthreads();
    sm = (red[4] + red[5]) + (red[6] + red[7]);
    if (tid < NPS) as[tid] = ex / sm;
    __syncthreads();

    float acc = 0.f;
#pragma unroll 16
    for (int n = 0; n < NPS; n++) acc = fmaf(as[n], fs[n][tid], acc);
    size_t o = (size_t)g * FF + tid;
    __nv_bfloat16 hi = __float2bfloat16(acc);
    g_shi[o] = hi;
    g_slo[o] = __float2bfloat16(acc - __bfloat162float(hi));
}

// ---------------- KG: generic bf16 hi/lo split mma GEMM --------------------
// C[M,N] = A[M,K] @ B^T[N,K] (+bias) via 3 bf16 products.
// BM=BN=128, BK=16, 8 warps, cp.async double buffering, ldmatrix.x4.
// ASRC: 0=g_ahi/g_alo  1=g_shi/g_slo
// BSRC: 0=g_bhi/g_blo  1=g_mwhi/g_mwlo  2=g_mthi/g_mtlo
// OUTSEL: 0 = g_z (+ rb/bias2)   [k5]
//         1 = g_w (no bias)      [k2]
//         2 = outp[:,H:] + mb, emits bf16 hi/lo of r  [k4]
#define LDSR 24                        // 16 + 8 pad (bf16); row = 48B
#define MATE (128 * LDSR)
#define STGE (4 * MATE)

template <int ASRC, int BSRC, int LDA, int LDB, int OUTSEL>
__global__ __launch_bounds__(256, 2) void kg_mma(
    int aoff, int boff, int K, float* __restrict__ outp,
    const float* __restrict__ bias, int use_b2)
{
    const __nv_bfloat16* __restrict__ Ahi = (ASRC == 0 ? g_ahi : g_shi) + aoff;
    const __nv_bfloat16* __restrict__ Alo = (ASRC == 0 ? g_alo : g_slo) + aoff;
    const __nv_bfloat16* __restrict__ Bhi =
        (BSRC == 0 ? g_bhi : BSRC == 1 ? g_mwhi : g_mthi) + boff;
    const __nv_bfloat16* __restrict__ Blo =
        (BSRC == 0 ? g_blo : BSRC == 1 ? g_mwlo : g_mtlo) + boff;

    __shared__ __align__(16) __nv_bfloat16 smem[2 * STGE];   // 49152 bytes
    int tid = threadIdx.x;
    int lane = tid & 31, wid = tid >> 5;
    int wm = wid >> 2, wn = wid & 3;          // 2 x 4 warp grid
    int nblk = blockIdx.x << 7, mblk = blockIdx.y << 7;
    int g8 = lane >> 2;
    int t2 = (lane & 3) << 1;

    int sr = tid >> 1;
    int sc = (tid & 1) << 3;
    uint32_t sbase;
    asm("{ .reg .u64 t; cvta.to.shared.u64 t, %1; cvt.u32.u64 %0, t; }"
        : "=r"(sbase) : "l"((const void*)smem));
    uint32_t soff = (uint32_t)(sr * LDSR + sc) * 2;

    uint32_t a_lm = (uint32_t)(((wm * 64) + (lane & 15)) * LDSR +
                               ((lane >> 4) << 3)) * 2;
    uint32_t b_lm = (uint32_t)(2 * MATE +
                               ((wn * 32) + (((lane >> 3) >> 1) << 3) + (lane & 7)) * LDSR +
                               (((lane >> 3) & 1) << 3)) * 2;

    float acc[4][4][4];
#pragma unroll
    for (int a = 0; a < 4; a++)
#pragma unroll
        for (int b = 0; b < 4; b++)
#pragma unroll
            for (int c = 0; c < 4; c++) acc[a][b][c] = 0.f;

    int nch = K >> 4;

#define LOAD_STAGE(T, ST) do {                                                  \
    int kg_ = (T) << 4;                                                         \
    uint32_t sb_ = sbase + (uint32_t)(ST) * (STGE * 2) + soff;                  \
    const __nv_bfloat16* a_ = Ahi + (size_t)(mblk + sr) * LDA + kg_ + sc;       \
    const __nv_bfloat16* b_ = Bhi + (size_t)(nblk + sr) * LDB + kg_ + sc;       \
    asm volatile("cp.async.cg.shared.global [%0], [%1], 16;"                    \
                 :: "r"(sb_), "l"(a_) : "memory");                              \
    asm volatile("cp.async.cg.shared.global [%0], [%1], 16;"                    \
                 :: "r"(sb_ + MATE * 2), "l"(Alo + (a_ - Ahi)) : "memory");     \
    asm volatile("cp.async.cg.shared.global [%0], [%1], 16;"                    \
                 :: "r"(sb_ + 2 * MATE * 2), "l"(b_) : "memory");               \
    asm volatile("cp.async.cg.shared.global [%0], [%1], 16;"                    \
                 :: "r"(sb_ + 3 * MATE * 2), "l"(Blo + (b_ - Bhi)) : "memory"); \
    asm volatile("cp.async.commit_group;" ::: "memory");                       \
} while (0)

#define LDSM_X4(r0, r1, r2, r3, addr)                                           \
    asm volatile("ldmatrix.sync.aligned.m8n8.x4.shared.b16 {%0,%1,%2,%3}, [%4];"\
        : "=r"(r0), "=r"(r1), "=r"(r2), "=r"(r3) : "r"(addr) : "memory")

    LOAD_STAGE(0, 0);
    asm volatile("cp.async.wait_group 0;" ::: "memory");
    __syncthreads();

    for (int t = 0; t < nch; t++) {
        if (t + 1 < nch) LOAD_STAGE(t + 1, (t + 1) & 1);

        uint32_t sb = sbase + (uint32_t)(t & 1) * (STGE * 2);
        uint32_t bh[4][2], bl[4][2];
#pragma unroll
        for (int p = 0; p < 2; p++) {
            uint32_t ba = sb + b_lm + (uint32_t)(p * 16 * LDSR) * 2;
            LDSM_X4(bh[2 * p][0], bh[2 * p][1], bh[2 * p + 1][0], bh[2 * p + 1][1], ba);
            LDSM_X4(bl[2 * p][0], bl[2 * p][1], bl[2 * p + 1][0], bl[2 * p + 1][1],
                    ba + (uint32_t)(MATE * 2));
        }
#pragma unroll
        for (int mt = 0; mt < 4; mt++) {
            uint32_t aa = sb + a_lm + (uint32_t)(mt * 16 * LDSR) * 2;
            uint32_t ahf[4], alf[4];
            LDSM_X4(ahf[0], ahf[1], ahf[2], ahf[3], aa);
            LDSM_X4(alf[0], alf[1], alf[2], alf[3], aa + (uint32_t)(MATE * 2));
#pragma unroll
            for (int nt = 0; nt < 4; nt++) {
                mma16816(acc[mt][nt], ahf, bh[nt]);
                mma16816(acc[mt][nt], ahf, bl[nt]);
                mma16816(acc[mt][nt], alf, bh[nt]);
            }
        }

        if (t + 1 < nch) {
            asm volatile("cp.async.wait_group 0;" ::: "memory");
            __syncthreads();
        }
    }
#undef LOAD_STAGE
#undef LDSM_X4

    // ---- epilogue
    const float* bp = (OUTSEL == 0) ? (use_b2 ? g_bias2 : bias) : bias;
#pragma unroll
    for (int mt = 0; mt < 4; mt++) {
#pragma unroll
        for (int nt = 0; nt < 4; nt++) {
            int m = mblk + wm * 64 + mt * 16 + g8;
            int n = nblk + wn * 32 + nt * 8 + t2;
            float b0 = (OUTSEL == 1) ? 0.f : bp[n];
            float b1 = (OUTSEL == 1) ? 0.f : bp[n + 1];
            float2 v0 = make_float2(acc[mt][nt][0] + b0, acc[mt][nt][1] + b1);
            float2 v1 = make_float2(acc[mt][nt][2] + b0, acc[mt][nt][3] + b1);
            if (OUTSEL == 0) {
                *(float2*)(g_z + (size_t)m * FOURH + n) = v0;
                *(float2*)(g_z + (size_t)(m + 8) * FOURH + n) = v1;
            } else if (OUTSEL == 1) {
                *(float2*)(g_w + (size_t)m * FF + n) = v0;
                *(float2*)(g_w + (size_t)(m + 8) * FF + n) = v1;
            } else {
                size_t o0 = (size_t)m * TWOH + HH + n;
                size_t o1 = (size_t)(m + 8) * TWOH + HH + n;
                *(float2*)(outp + o0) = v0;
                *(float2*)(outp + o1) = v1;
                __nv_bfloat16 h0 = __float2bfloat16(v0.x);
                __nv_bfloat16 h1 = __float2bfloat16(v0.y);
                __nv_bfloat16 h2 = __float2bfloat16(v1.x);
                __nv_bfloat16 h3 = __float2bfloat16(v1.y);
                *(__nv_bfloat162*)(g_ahi + o0) = __nv_bfloat162{h0, h1};
                *(__nv_bfloat162*)(g_ahi + o1) = __nv_bfloat162{h2, h3};
                *(__nv_bfloat162*)(g_alo + o0) = __nv_bfloat162{
                    __float2bfloat16(v0.x - __bfloat162float(h0)),
                    __float2bfloat16(v0.y - __bfloat162float(h1))};
                *(__nv_bfloat162*)(g_alo + o1) = __nv_bfloat162{
                    __float2bfloat16(v1.x - __bfloat162float(h2)),
                    __float2bfloat16(v1.y - __bfloat162float(h3))};
            }
        }
    }
}

// ---------------- launch ----------------------------------------------------
extern "C" void kernel_launch(void* const* d_in, const int* in_sizes, int n_in,
                              void* d_out, int out_size) {
    const float* feat = (const float*)d_in[0];   // features (1, N, F)
    const float* wts  = (const float*)d_in[1];   // weights  (1, N)
    const float* MW   = (const float*)d_in[3];   // m_weight (F, H)
    const float* mb   = (const float*)d_in[4];   // m_bias   (H,)
    const float* R    = (const float*)d_in[5];   // recurrent_kernel (2H, 4H)
    const float* rb   = (const float*)d_in[6];   // recurrent_bias   (4H,)
    float* out = (float*)d_out;                  // q_star (1, G, 2H)

    // ---- prologue (ordered so launch #4 = k3_seg for the profiler)
    k0_init <<<1, HH>>>(rb);
    k0_w1   <<<16, 256>>>(MW);
    kconv_MW<<<dim3(HH / 32, FF / 32), 256>>>(MW);
    k3_seg  <<<GG, 128>>>(feat, wts, 1);
    kg_mma<1, 2, FF, FF, 2><<<dim3(HH / 128, GG / 128), 256>>>(
        0, 0, FF, out, mb, 0);                              // k4: r1
    kconv_R <<<dim3(TWOH / 32, FOURH / 32), 256>>>(R);
    k0_bcast<<<(GG * HH) / 256, 256>>>();
    k0_bias2a<<<64, 256>>>(R);
    k0_bias2b<<<FOURH / 256, 256>>>(rb);

    // ---- iteration 2 (h1 folded into bias2 -> half-K GEMM over r only)
    kg_mma<0, 0, TWOH, TWOH, 0><<<dim3(FOURH / 128, GG / 128), 256>>>(
        HH, HH, HH, out, rb, 1);                            // k5
    k1_gates<<<(GG * HH) / 256, 256>>>(out);
    kg_mma<0, 1, TWOH, HH, 1><<<dim3(FF / 128, GG / 128), 256>>>(
        0, 0, HH, out, rb, 0);                              // k2: w
    k3_seg  <<<GG, 128>>>(feat, wts, 0);
    kg_mma<1, 2, FF, FF, 2><<<dim3(HH / 128, GG / 128), 256>>>(
        0, 0, FF, out, mb, 0);                              // k4: r2

    // ---- iteration 3 (full K = 2H)
    kg_mma<0, 0, TWOH, TWOH, 0><<<dim3(FOURH / 128, GG / 128), 256>>>(
        0, 0, TWOH, out, rb, 0);                            // k5
    k1_gates<<<(GG * HH) / 256, 256>>>(out);
    kg_mma<0, 1, TWOH, HH, 1><<<dim3(FF / 128, GG / 128), 256>>>(
        0, 0, HH, out, rb, 0);                              // k2: w
    k3_seg  <<<GG, 128>>>(feat, wts, 0);
    kg_mma<1, 2, FF, FF, 2><<<dim3(HH / 128, GG / 128), 256>>>(
        0, 0, FF, out, mb, 0);                              // k4: r3
}

// round 10
// speedup vs baseline: 2.2446x; 1.0375x over previous
#include <cuda_runtime.h>
#include <cuda_bf16.h>
#include <math.h>
#include <stdint.h>

#define GG    4096
#define HH    512
#define FF    128
#define NPS   64
#define TWOH  1024
#define FOURH 2048

// ---------------- scratch (device globals; no allocation allowed) ----------
// NOTE: device-global symbols must only be referenced from DEVICE code.
__device__ float g_z[GG * FOURH];     // z = q_star @ R + bias
__device__ float g_c[GG * HH];        // LSTM cell state
__device__ float g_w[GG * FF];        // w_g = h_g @ MW^T
__device__ float g_h1[HH];
__device__ float g_c1[HH];
__device__ float g_w1[FF];
__device__ float g_bias2[FOURH];      // rb + h1 @ R_top
__device__ float g_b2p[8 * FOURH];    // split-K partials for bias2
__device__ __nv_bfloat16 g_ahi[GG * TWOH];      // q_star hi (bf16)
__device__ __nv_bfloat16 g_alo[GG * TWOH];      // q_star lo (bf16)
__device__ __nv_bfloat16 g_bhi[FOURH * TWOH];   // R^T hi   [n][k]
__device__ __nv_bfloat16 g_blo[FOURH * TWOH];   // R^T lo   [n][k]
__device__ __nv_bfloat16 g_shi[GG * FF];        // s hi
__device__ __nv_bfloat16 g_slo[GG * FF];        // s lo
__device__ __nv_bfloat16 g_mwhi[FF * HH];       // MW hi    [f][k]
__device__ __nv_bfloat16 g_mwlo[FF * HH];
__device__ __nv_bfloat16 g_mthi[HH * FF];       // MW^T hi  [h][f]
__device__ __nv_bfloat16 g_mtlo[HH * FF];

__device__ __forceinline__ float hsig(float x) {
    return __saturatef(fmaf(0.2f, x, 0.5f));
}
__device__ __forceinline__ void mma16816(float* c, const uint32_t* a,
                                         const uint32_t* b) {
    asm volatile(
        "mma.sync.aligned.m16n8k16.row.col.f32.bf16.bf16.f32 "
        "{%0,%1,%2,%3}, {%4,%5,%6,%7}, {%8,%9}, {%0,%1,%2,%3};"
        : "+f"(c[0]), "+f"(c[1]), "+f"(c[2]), "+f"(c[3])
        : "r"(a[0]), "r"(a[1]), "r"(a[2]), "r"(a[3]), "r"(b[0]), "r"(b[1]));
}

// ---------------- K0: iteration-1 analytic prologue ------------------------
__global__ void k0_init(const float* __restrict__ rb) {
    int h = threadIdx.x;                      // 512 threads
    float zi = rb[h], zc = rb[2 * HH + h], zo = rb[3 * HH + h];
    float c  = hsig(zi) * tanhf(zc);
    g_c1[h] = c;
    g_h1[h] = hsig(zo) * tanhf(c);
}
__global__ __launch_bounds__(256) void k0_bcast() {
    int i = blockIdx.x * 256 + threadIdx.x;
    g_c[i] = g_c1[i & (HH - 1)];
}
// w1[f] = sum_k MW[f,k] * h1[k] — one warp per f
__global__ __launch_bounds__(256) void k0_w1(const float* __restrict__ MW) {
    int warp = blockIdx.x * 8 + (threadIdx.x >> 5);   // 0..127
    int lane = threadIdx.x & 31;
    const float* row = MW + (size_t)warp * HH;
    float acc = 0.f;
#pragma unroll 4
    for (int k = lane; k < HH; k += 32) acc = fmaf(row[k], g_h1[k], acc);
#pragma unroll
    for (int o = 16; o > 0; o >>= 1) acc += __shfl_xor_sync(0xffffffffu, acc, o);
    if (lane == 0) g_w1[warp] = acc;
}
__global__ __launch_bounds__(256) void k0_bias2a(const float* __restrict__ R) {
    int id = blockIdx.x * 256 + threadIdx.x;  // 16384
    int n  = id & (FOURH - 1);
    int ch = id >> 11;                        // 0..7
    const float* hp = g_h1 + ch * 64;
    const float* rp = R + (size_t)(ch * 64) * FOURH + n;
    float acc = 0.f;
#pragma unroll 8
    for (int k = 0; k < 64; k++) acc = fmaf(hp[k], rp[(size_t)k * FOURH], acc);
    g_b2p[ch * FOURH + n] = acc;
}
__global__ __launch_bounds__(256) void k0_bias2b(const float* __restrict__ rb) {
    int n = blockIdx.x * 256 + threadIdx.x;   // 2048
    float a = rb[n];
#pragma unroll
    for (int c = 0; c < 8; c++) a += g_b2p[c * FOURH + n];
    g_bias2[n] = a;
}

// ---------------- Kconv_R: R fp32 -> R^T hi/lo bf16 [2048][1024] -----------
__global__ __launch_bounds__(256) void kconv_R(const float* __restrict__ R) {
    __shared__ float tile[32][33];
    int k0 = blockIdx.x * 32, n0 = blockIdx.y * 32;
    int tx = threadIdx.x & 31, ty = threadIdx.x >> 5;  // 32 x 8
#pragma unroll
    for (int i = ty; i < 32; i += 8)
        tile[i][tx] = R[(size_t)(k0 + i) * FOURH + n0 + tx];
    __syncthreads();
#pragma unroll
    for (int i = ty; i < 32; i += 8) {
        float v = tile[tx][i];                 // = R[k0+tx][n0+i]
        __nv_bfloat16 hi = __float2bfloat16(v);
        size_t o = (size_t)(n0 + i) * TWOH + k0 + tx;
        g_bhi[o] = hi;
        g_blo[o] = __float2bfloat16(v - __bfloat162float(hi));
    }
}

// ---------------- Kconv_MW: MW fp32 -> bf16 hi/lo (direct + transposed) ----
__global__ __launch_bounds__(256) void kconv_MW(const float* __restrict__ MW) {
    __shared__ float tile[32][33];
    int h0 = blockIdx.x * 32, f0 = blockIdx.y * 32;
    int tx = threadIdx.x & 31, ty = threadIdx.x >> 5;
#pragma unroll
    for (int i = ty; i < 32; i += 8) {
        float v = MW[(size_t)(f0 + i) * HH + h0 + tx];
        tile[i][tx] = v;
        __nv_bfloat16 hi = __float2bfloat16(v);
        size_t o = (size_t)(f0 + i) * HH + h0 + tx;
        g_mwhi[o] = hi;
        g_mwlo[o] = __float2bfloat16(v - __bfloat162float(hi));
    }
    __syncthreads();
#pragma unroll
    for (int i = ty; i < 32; i += 8) {
        float v = tile[tx][i];                 // = MW[f0+tx][h0+i]
        __nv_bfloat16 hi = __float2bfloat16(v);
        size_t o = (size_t)(h0 + i) * FF + f0 + tx;
        g_mthi[o] = hi;
        g_mtlo[o] = __float2bfloat16(v - __bfloat162float(hi));
    }
}

// ---------------- K1: LSTM gates (+ emits bf16 hi/lo of h) -----------------
__global__ __launch_bounds__(256) void k1_gates(float* __restrict__ out) {
    int i  = blockIdx.x * 256 + threadIdx.x;
    int hh = i & (HH - 1);
    int g  = i >> 9;
    const float* zr = g_z + (size_t)g * FOURH;
    float zi = zr[hh], zf = zr[HH + hh], zc = zr[2 * HH + hh], zo = zr[3 * HH + hh];
    float c = hsig(zf) * g_c[i] + hsig(zi) * tanhf(zc);
    g_c[i] = c;
    float h = hsig(zo) * tanhf(c);
    size_t o = (size_t)g * TWOH + hh;
    out[o] = h;
    __nv_bfloat16 hi = __float2bfloat16(h);
    g_ahi[o] = hi;
    g_alo[o] = __float2bfloat16(h - __bfloat162float(hi));
}

// ---------------- K3: per-segment softmax + weighted feature sum -----------
// v2: 256 threads, cp.async feature staging (full MLP, no reg coupling).
__global__ __launch_bounds__(256) void k3_seg(const float* __restrict__ feat,
                                              const float* __restrict__ wts,
                                              int use_w1) {
    int g = blockIdx.x;
    int tid = threadIdx.x;
    __shared__ __align__(16) float fs[NPS][FF + 4];
    __shared__ float ws[FF];
    __shared__ float as[NPS];
    __shared__ float red[16];
    __shared__ float red2[FF];

    // ---- stage features via cp.async: 2048 x 16B, 8 per thread
    const float* fp = feat + (size_t)g * NPS * FF;
    uint32_t sb;
    asm("{ .reg .u64 t; cvta.to.shared.u64 t, %1; cvt.u32.u64 %0, t; }"
        : "=r"(sb) : "l"((const void*)fs));
#pragma unroll
    for (int i = 0; i < 8; i++) {
        int idx = tid + (i << 8);             // 0..2047
        int node = idx >> 5;
        int col  = (idx & 31) << 2;
        uint32_t dst = sb + (uint32_t)(node * (FF + 4) + col) * 4;
        asm volatile("cp.async.cg.shared.global [%0], [%1], 16;"
                     :: "r"(dst), "l"(fp + (size_t)idx * 4) : "memory");
    }
    asm volatile("cp.async.commit_group;" ::: "memory");
    if (tid < FF) {
        const float* wp = use_w1 ? g_w1 : (g_w + (size_t)g * FF);
        ws[tid] = wp[tid];
    }
    asm volatile("cp.async.wait_group 0;" ::: "memory");
    __syncthreads();

    // ---- e_n = f_n . w (threads 0..63)
    float e = -1e30f;
    if (tid < NPS) {
        float acc = 0.f;
#pragma unroll
        for (int f = 0; f < FF; f += 4) {
            float4 fv = *(const float4*)&fs[tid][f];
            float4 wv = *(const float4*)&ws[f];
            acc = fmaf(fv.x, wv.x, acc); acc = fmaf(fv.y, wv.y, acc);
            acc = fmaf(fv.z, wv.z, acc); acc = fmaf(fv.w, wv.w, acc);
        }
        e = acc;
    }
    float mx = e;
#pragma unroll
    for (int o = 16; o > 0; o >>= 1) mx = fmaxf(mx, __shfl_xor_sync(0xffffffffu, mx, o));
    if ((tid & 31) == 0) red[tid >> 5] = mx;
    __syncthreads();
    mx = fmaxf(fmaxf(red[0], red[1]), -1e30f);   // only warps 0,1 hold real e

    float ex = 0.f;
    if (tid < NPS) ex = __expf(e - mx) * wts[(size_t)g * NPS + tid];
    float sm = ex;
#pragma unroll
    for (int o = 16; o > 0; o >>= 1) sm += __shfl_xor_sync(0xffffffffu, sm, o);
    if ((tid & 31) == 0) red[8 + (tid >> 5)] = sm;
    __syncthreads();
    sm = red[8] + red[9];
    if (tid < NPS) as[tid] = ex / sm;
    __syncthreads();

    // ---- s_f = sum_n a_n f[n][f]  (256 threads: 2 halves of 32 nodes)
    int col  = tid & (FF - 1);
    int half = tid >> 7;
    int nb   = half << 5;
    float acc = 0.f;
#pragma unroll 16
    for (int n = 0; n < 32; n++) acc = fmaf(as[nb + n], fs[nb + n][col], acc);
    if (half) red2[col] = acc;
    __syncthreads();
    if (!half) {
        float v = acc + red2[col];
        size_t o = (size_t)g * FF + col;
        __nv_bfloat16 hi = __float2bfloat16(v);
        g_shi[o] = hi;
        g_slo[o] = __float2bfloat16(v - __bfloat162float(hi));
    }
}

// ---------------- KG: generic bf16 hi/lo split mma GEMM --------------------
// C[M,N] = A[M,K] @ B^T[N,K] (+bias) via 3 bf16 products.
// BM=BN=128, BK=16, 8 warps, cp.async double buffering, ldmatrix.x4.
#define LDSR 24                        // 16 + 8 pad (bf16); row = 48B
#define MATE (128 * LDSR)
#define STGE (4 * MATE)

template <int ASRC, int BSRC, int LDA, int LDB, int OUTSEL>
__global__ __launch_bounds__(256, 2) void kg_mma(
    int aoff, int boff, int K, float* __restrict__ outp,
    const float* __restrict__ bias, int use_b2)
{
    const __nv_bfloat16* __restrict__ Ahi = (ASRC == 0 ? g_ahi : g_shi) + aoff;
    const __nv_bfloat16* __restrict__ Alo = (ASRC == 0 ? g_alo : g_slo) + aoff;
    const __nv_bfloat16* __restrict__ Bhi =
        (BSRC == 0 ? g_bhi : BSRC == 1 ? g_mwhi : g_mthi) + boff;
    const __nv_bfloat16* __restrict__ Blo =
        (BSRC == 0 ? g_blo : BSRC == 1 ? g_mwlo : g_mtlo) + boff;

    __shared__ __align__(16) __nv_bfloat16 smem[2 * STGE];   // 49152 bytes
    int tid = threadIdx.x;
    int lane = tid & 31, wid = tid >> 5;
    int wm = wid >> 2, wn = wid & 3;          // 2 x 4 warp grid
    int nblk = blockIdx.x << 7, mblk = blockIdx.y << 7;
    int g8 = lane >> 2;
    int t2 = (lane & 3) << 1;

    int sr = tid >> 1;
    int sc = (tid & 1) << 3;
    uint32_t sbase;
    asm("{ .reg .u64 t; cvta.to.shared.u64 t, %1; cvt.u32.u64 %0, t; }"
        : "=r"(sbase) : "l"((const void*)smem));
    uint32_t soff = (uint32_t)(sr * LDSR + sc) * 2;

    uint32_t a_lm = (uint32_t)(((wm * 64) + (lane & 15)) * LDSR +
                               ((lane >> 4) << 3)) * 2;
    uint32_t b_lm = (uint32_t)(2 * MATE +
                               ((wn * 32) + (((lane >> 3) >> 1) << 3) + (lane & 7)) * LDSR +
                               (((lane >> 3) & 1) << 3)) * 2;

    float acc[4][4][4];
#pragma unroll
    for (int a = 0; a < 4; a++)
#pragma unroll
        for (int b = 0; b < 4; b++)
#pragma unroll
            for (int c = 0; c < 4; c++) acc[a][b][c] = 0.f;

    int nch = K >> 4;

#define LOAD_STAGE(T, ST) do {                                                  \
    int kg_ = (T) << 4;                                                         \
    uint32_t sb_ = sbase + (uint32_t)(ST) * (STGE * 2) + soff;                  \
    const __nv_bfloat16* a_ = Ahi + (size_t)(mblk + sr) * LDA + kg_ + sc;       \
    const __nv_bfloat16* b_ = Bhi + (size_t)(nblk + sr) * LDB + kg_ + sc;       \
    asm volatile("cp.async.cg.shared.global [%0], [%1], 16;"                    \
                 :: "r"(sb_), "l"(a_) : "memory");                              \
    asm volatile("cp.async.cg.shared.global [%0], [%1], 16;"                    \
                 :: "r"(sb_ + MATE * 2), "l"(Alo + (a_ - Ahi)) : "memory");     \
    asm volatile("cp.async.cg.shared.global [%0], [%1], 16;"                    \
                 :: "r"(sb_ + 2 * MATE * 2), "l"(b_) : "memory");               \
    asm volatile("cp.async.cg.shared.global [%0], [%1], 16;"                    \
                 :: "r"(sb_ + 3 * MATE * 2), "l"(Blo + (b_ - Bhi)) : "memory"); \
    asm volatile("cp.async.commit_group;" ::: "memory");                       \
} while (0)

#define LDSM_X4(r0, r1, r2, r3, addr)                                           \
    asm volatile("ldmatrix.sync.aligned.m8n8.x4.shared.b16 {%0,%1,%2,%3}, [%4];"\
        : "=r"(r0), "=r"(r1), "=r"(r2), "=r"(r3) : "r"(addr) : "memory")

    LOAD_STAGE(0, 0);
    asm volatile("cp.async.wait_group 0;" ::: "memory");
    __syncthreads();

    for (int t = 0; t < nch; t++) {
        if (t + 1 < nch) LOAD_STAGE(t + 1, (t + 1) & 1);

        uint32_t sb = sbase + (uint32_t)(t & 1) * (STGE * 2);
        uint32_t bh[4][2], bl[4][2];
#pragma unroll
        for (int p = 0; p < 2; p++) {
            uint32_t ba = sb + b_lm + (uint32_t)(p * 16 * LDSR) * 2;
            LDSM_X4(bh[2 * p][0], bh[2 * p][1], bh[2 * p + 1][0], bh[2 * p + 1][1], ba);
            LDSM_X4(bl[2 * p][0], bl[2 * p][1], bl[2 * p + 1][0], bl[2 * p + 1][1],
                    ba + (uint32_t)(MATE * 2));
        }
#pragma unroll
        for (int mt = 0; mt < 4; mt++) {
            uint32_t aa = sb + a_lm + (uint32_t)(mt * 16 * LDSR) * 2;
            uint32_t ahf[4], alf[4];
            LDSM_X4(ahf[0], ahf[1], ahf[2], ahf[3], aa);
            LDSM_X4(alf[0], alf[1], alf[2], alf[3], aa + (uint32_t)(MATE * 2));
#pragma unroll
            for (int nt = 0; nt < 4; nt++) {
                mma16816(acc[mt][nt], ahf, bh[nt]);
                mma16816(acc[mt][nt], ahf, bl[nt]);
                mma16816(acc[mt][nt], alf, bh[nt]);
            }
        }

        if (t + 1 < nch) {
            asm volatile("cp.async.wait_group 0;" ::: "memory");
            __syncthreads();
        }
    }
#undef LOAD_STAGE
#undef LDSM_X4

    // ---- epilogue
    const float* bp = (OUTSEL == 0) ? (use_b2 ? g_bias2 : bias) : bias;
#pragma unroll
    for (int mt = 0; mt < 4; mt++) {
#pragma unroll
        for (int nt = 0; nt < 4; nt++) {
            int m = mblk + wm * 64 + mt * 16 + g8;
            int n = nblk + wn * 32 + nt * 8 + t2;
            float b0 = (OUTSEL == 1) ? 0.f : bp[n];
            float b1 = (OUTSEL == 1) ? 0.f : bp[n + 1];
            float2 v0 = make_float2(acc[mt][nt][0] + b0, acc[mt][nt][1] + b1);
            float2 v1 = make_float2(acc[mt][nt][2] + b0, acc[mt][nt][3] + b1);
            if (OUTSEL == 0) {
                *(float2*)(g_z + (size_t)m * FOURH + n) = v0;
                *(float2*)(g_z + (size_t)(m + 8) * FOURH + n) = v1;
            } else if (OUTSEL == 1) {
                *(float2*)(g_w + (size_t)m * FF + n) = v0;
                *(float2*)(g_w + (size_t)(m + 8) * FF + n) = v1;
            } else {
                size_t o0 = (size_t)m * TWOH + HH + n;
                size_t o1 = (size_t)(m + 8) * TWOH + HH + n;
                *(float2*)(outp + o0) = v0;
                *(float2*)(outp + o1) = v1;
                __nv_bfloat16 h0 = __float2bfloat16(v0.x);
                __nv_bfloat16 h1 = __float2bfloat16(v0.y);
                __nv_bfloat16 h2 = __float2bfloat16(v1.x);
                __nv_bfloat16 h3 = __float2bfloat16(v1.y);
                *(__nv_bfloat162*)(g_ahi + o0) = __nv_bfloat162{h0, h1};
                *(__nv_bfloat162*)(g_ahi + o1) = __nv_bfloat162{h2, h3};
                *(__nv_bfloat162*)(g_alo + o0) = __nv_bfloat162{
                    __float2bfloat16(v0.x - __bfloat162float(h0)),
                    __float2bfloat16(v0.y - __bfloat162float(h1))};
                *(__nv_bfloat162*)(g_alo + o1) = __nv_bfloat162{
                    __float2bfloat16(v1.x - __bfloat162float(h2)),
                    __float2bfloat16(v1.y - __bfloat162float(h3))};
            }
        }
    }
}

// ---------------- launch ----------------------------------------------------
extern "C" void kernel_launch(void* const* d_in, const int* in_sizes, int n_in,
                              void* d_out, int out_size) {
    const float* feat = (const float*)d_in[0];   // features (1, N, F)
    const float* wts  = (const float*)d_in[1];   // weights  (1, N)
    const float* MW   = (const float*)d_in[3];   // m_weight (F, H)
    const float* mb   = (const float*)d_in[4];   // m_bias   (H,)
    const float* R    = (const float*)d_in[5];   // recurrent_kernel (2H, 4H)
    const float* rb   = (const float*)d_in[6];   // recurrent_bias   (4H,)
    float* out = (float*)d_out;                  // q_star (1, G, 2H)

    // ---- prologue (launch #4 = k3_seg for the profiler)
    k0_init <<<1, HH>>>(rb);
    k0_w1   <<<16, 256>>>(MW);
    kconv_MW<<<dim3(HH / 32, FF / 32), 256>>>(MW);
    k3_seg  <<<GG, 256>>>(feat, wts, 1);
    kg_mma<1, 2, FF, FF, 2><<<dim3(HH / 128, GG / 128), 256>>>(
        0, 0, FF, out, mb, 0);                              // k4: r1
    kconv_R <<<dim3(TWOH / 32, FOURH / 32), 256>>>(R);
    k0_bcast<<<(GG * HH) / 256, 256>>>();
    k0_bias2a<<<64, 256>>>(R);
    k0_bias2b<<<FOURH / 256, 256>>>(rb);

    // ---- iteration 2 (h1 folded into bias2 -> half-K GEMM over r only)
    kg_mma<0, 0, TWOH, TWOH, 0><<<dim3(FOURH / 128, GG / 128), 256>>>(
        HH, HH, HH, out, rb, 1);                            // k5
    k1_gates<<<(GG * HH) / 256, 256>>>(out);
    kg_mma<0, 1, TWOH, HH, 1><<<dim3(FF / 128, GG / 128), 256>>>(
        0, 0, HH, out, rb, 0);                              // k2: w
    k3_seg  <<<GG, 256>>>(feat, wts, 0);
    kg_mma<1, 2, FF, FF, 2><<<dim3(HH / 128, GG / 128), 256>>>(
        0, 0, FF, out, mb, 0);                              // k4: r2

    // ---- iteration 3 (full K = 2H)
    kg_mma<0, 0, TWOH, TWOH, 0><<<dim3(FOURH / 128, GG / 128), 256>>>(
        0, 0, TWOH, out, rb, 0);                            // k5
    k1_gates<<<(GG * HH) / 256, 256>>>(out);
    kg_mma<0, 1, TWOH, HH, 1><<<dim3(FF / 128, GG / 128), 256>>>(
        0, 0, HH, out, rb, 0);                              // k2: w
    k3_seg  <<<GG, 256>>>(feat, wts, 0);
    kg_mma<1, 2, FF, FF, 2><<<dim3(HH / 128, GG / 128), 256>>>(
        0, 0, FF, out, mb, 0);                              // k4: r3
}